// round 5
// baseline (speedup 1.0000x reference)
#include <cuda_runtime.h>

#define N_EDGES   400000
#define TE        128
#define NBLK      (N_EDGES / TE)   // 3125, exact
#define WN        576              // WEIGHT_NUMEL
#define SHS       129              // sH row stride (odd: conflict-free both phases)
#define C3F       0.5773502691896257f
// S0 = sqrt(1/24) * (1/8 wvec scale) * (1/4 output scale) = sqrt(1/24)/32
#define S0F       0.006378879538497861f
#define SILU_NORM 1.6791767923989418f

typedef unsigned long long u64;

__device__ __forceinline__ void ffma2(u64 &d, u64 a, u64 b) {
  asm("fma.rn.f32x2 %0, %1, %2, %0;" : "+l"(d) : "l"(a), "l"(b));
}
__device__ __forceinline__ u64 dup2(float x) {
  u64 r; asm("mov.b64 %0, {%1, %1};" : "=l"(r) : "f"(x)); return r;
}
__device__ __forceinline__ void unpack2(u64 v, float &lo, float &hi) {
  asm("mov.b64 {%0, %1}, %2;" : "=f"(lo), "=f"(hi) : "l"(v));
}

// Shared layout (floats):
#define OFF_H   0                      // 64*SHS   dist^T / h^T [k][e]
#define OFF_W0  (64 * SHS)             // 64*64    W1 / W2 chunk buf0
#define OFF_W1  (OFF_W0 + 4096)        // 64*64    W2 chunk buf1
#define OFF_X   (OFF_W1 + 4096)        // 128*41   gathered node features
#define OFF_Y   (OFF_X + 128 * 41)     // 128*5    edge_attr
#define OFF_SRC (OFF_Y + 128 * 5)      // 128 ints
#define OFF_DST (OFF_SRC + 128)        // 128 ints
#define SMEM_FLOATS (OFF_DST + 128)
#define SMEM_BYTES  (SMEM_FLOATS * 4)

// Permuted copy of W2 (64 x 576), column order matched to per-thread slices.
__device__ float g_W2p[64 * WN];

// mprime = (g*4 + r)*16 + j  ->  original column m of W2.
__global__ void permute_w2(const float* __restrict__ W2) {
  int mp = blockIdx.x * blockDim.x + threadIdx.x;
  if (mp >= WN) return;
  int j = mp & 15, gr = mp >> 4, g = gr >> 2, r = gr & 3;
  int m;
  if (g < 4)       m = j * 16 + r + 4 * g;
  else if (g < 6)  m = 448 + (j & 7) * 16 + r + 4 * ((g - 4) * 2 + (j >> 3));
  else if (g < 8)  m = 256 + j * 8 + 2 * r + (g - 6);
  else             m = 384 + (j & 7) * 8 + 2 * r + (j >> 3);
  for (int k = 0; k < 64; k++)
    g_W2p[k * WN + mp] = W2[k * WN + m];
}

// Stage one 64x64 W2 chunk into a smem buffer (128 threads).
__device__ __forceinline__ void stage_chunk(int t, float* dst, int G) {
  #pragma unroll
  for (int it = 0; it < 8; it++) {
    int i4 = t + it * 128;
    int kk = i4 >> 4, cc = i4 & 15;
    ((float4*)dst)[i4] = *(const float4*)(g_W2p + kk * WN + G * 64 + cc * 4);
  }
}

template <int G>
__device__ __forceinline__ void do_chunk(
    int t, int e, int r,
    float* __restrict__ sm,
    const float y0_[4], const float y1x_[4], const float y1y_[4], const float y1z_[4],
    float (&acc0)[4][4], float (&a1)[4][6])
{
  const float* sH = sm + OFF_H;
  const float* sX = sm + OFF_X;
  const float* sWc = sm + ((G & 1) ? OFF_W0 : OFF_W1);  // chunk G lives here
  float*       sWn = sm + ((G & 1) ? OFF_W1 : OFF_W0);  // next chunk staged here

  __syncthreads();  // chunk G data ready; prior reads of sWn complete
  if (G < 8) stage_chunk(t, sWn, G + 1);

  u64 wv2[4][8];
  #pragma unroll
  for (int ee = 0; ee < 4; ee++)
    #pragma unroll
    for (int j = 0; j < 8; j++) wv2[ee][j] = 0ull;

  #pragma unroll 2
  for (int k = 0; k < 64; k++) {
    u64 h0 = dup2(sH[k * SHS + e]);
    u64 h1 = dup2(sH[k * SHS + e + 32]);
    u64 h2 = dup2(sH[k * SHS + e + 64]);
    u64 h3 = dup2(sH[k * SHS + e + 96]);
    const ulonglong2* wp = (const ulonglong2*)(sWc + k * 64 + r * 16);
    ulonglong2 p0 = wp[0], p1 = wp[1], p2 = wp[2], p3 = wp[3];
    ffma2(wv2[0][0], h0, p0.x);  ffma2(wv2[0][1], h0, p0.y);
    ffma2(wv2[0][2], h0, p1.x);  ffma2(wv2[0][3], h0, p1.y);
    ffma2(wv2[0][4], h0, p2.x);  ffma2(wv2[0][5], h0, p2.y);
    ffma2(wv2[0][6], h0, p3.x);  ffma2(wv2[0][7], h0, p3.y);
    ffma2(wv2[1][0], h1, p0.x);  ffma2(wv2[1][1], h1, p0.y);
    ffma2(wv2[1][2], h1, p1.x);  ffma2(wv2[1][3], h1, p1.y);
    ffma2(wv2[1][4], h1, p2.x);  ffma2(wv2[1][5], h1, p2.y);
    ffma2(wv2[1][6], h1, p3.x);  ffma2(wv2[1][7], h1, p3.y);
    ffma2(wv2[2][0], h2, p0.x);  ffma2(wv2[2][1], h2, p0.y);
    ffma2(wv2[2][2], h2, p1.x);  ffma2(wv2[2][3], h2, p1.y);
    ffma2(wv2[2][4], h2, p2.x);  ffma2(wv2[2][5], h2, p2.y);
    ffma2(wv2[2][6], h2, p3.x);  ffma2(wv2[2][7], h2, p3.y);
    ffma2(wv2[3][0], h3, p0.x);  ffma2(wv2[3][1], h3, p0.y);
    ffma2(wv2[3][2], h3, p1.x);  ffma2(wv2[3][3], h3, p1.y);
    ffma2(wv2[3][4], h3, p2.x);  ffma2(wv2[3][5], h3, p2.y);
    ffma2(wv2[3][6], h3, p3.x);  ffma2(wv2[3][7], h3, p3.y);
  }

  #pragma unroll
  for (int ee = 0; ee < 4; ee++) {
    const int eidx = e + 32 * ee;
    float wv[16];
    #pragma unroll
    for (int j = 0; j < 8; j++) unpack2(wv2[ee][j], wv[2 * j], wv[2 * j + 1]);

    if (G < 4) {                 // w1: out0[w=r+4G] += y0 * sum_u x0[u]*wv[u]
      float s = 0.0f;
      #pragma unroll
      for (int j = 0; j < 16; j++) s += sX[eidx * 41 + j] * wv[j];
      acc0[ee][G < 4 ? G : 0] += y0_[ee] * s;
    } else if (G < 6) {          // w4: out0 += C3 * sum_u z4[u]*wv (z4 recomputed)
      float sA = 0.0f, sB = 0.0f;
      #pragma unroll
      for (int u = 0; u < 8; u++) {
        float z = sX[eidx * 41 + 16 + 3 * u + 0] * y1x_[ee]
                + sX[eidx * 41 + 16 + 3 * u + 1] * y1y_[ee]
                + sX[eidx * 41 + 16 + 3 * u + 2] * y1z_[ee];
        sA += z * wv[u];  sB += z * wv[8 + u];
      }
      acc0[ee][2 * (G - 4) + 0] += C3F * sA;
      acc0[ee][2 * (G - 4) + 1] += C3F * sB;
    } else if (G < 8) {          // w2: q = sum_u x0[u]*wv; out1[w][i] += q*y1[i]
      float q = 0.0f;
      #pragma unroll
      for (int j = 0; j < 16; j++) q += sX[eidx * 41 + j] * wv[j];
      int b = 3 * (G - 6);
      a1[ee][b + 0] += q * y1x_[ee];
      a1[ee][b + 1] += q * y1y_[ee];
      a1[ee][b + 2] += q * y1z_[ee];
    } else {                     // w3: out1[w][i] += y0 * sum_u x1[u][i]*wv
      float s0 = 0, s1 = 0, s2 = 0, t0 = 0, t1 = 0, t2 = 0;
      #pragma unroll
      for (int u = 0; u < 8; u++) {
        float x0v = sX[eidx * 41 + 16 + 3 * u + 0];
        float x1v = sX[eidx * 41 + 16 + 3 * u + 1];
        float x2v = sX[eidx * 41 + 16 + 3 * u + 2];
        s0 += x0v * wv[u];     s1 += x1v * wv[u];     s2 += x2v * wv[u];
        t0 += x0v * wv[8 + u]; t1 += x1v * wv[8 + u]; t2 += x2v * wv[8 + u];
      }
      a1[ee][0] += y0_[ee] * s0; a1[ee][1] += y0_[ee] * s1; a1[ee][2] += y0_[ee] * s2;
      a1[ee][3] += y0_[ee] * t0; a1[ee][4] += y0_[ee] * t1; a1[ee][5] += y0_[ee] * t2;
    }
  }
}

__global__ __launch_bounds__(128, 2) void fused_conv(
    const float* __restrict__ node_input,
    const int*   __restrict__ edge_src,
    const int*   __restrict__ edge_dst,
    const float* __restrict__ edge_attr,
    const float* __restrict__ dist,
    const float* __restrict__ W1,
    float* __restrict__ out)
{
  extern __shared__ float sm[];
  float* sH  = sm + OFF_H;
  float* sW0 = sm + OFF_W0;
  float* sX  = sm + OFF_X;
  float* sY  = sm + OFF_Y;
  int*   sSrc = (int*)(sm + OFF_SRC);
  int*   sDst = (int*)(sm + OFF_DST);

  const int t = threadIdx.x;
  const int e = t & 31;
  const int r = t >> 5;
  const long e0 = (long)blockIdx.x * TE;

  sDst[t] = edge_dst[e0 + t];
  sSrc[t] = edge_src[e0 + t];

  // dist tile, transposed store (stride SHS odd -> conflict-free)
  #pragma unroll 4
  for (int idx = t; idx < 128 * 64; idx += 128) {
    int er = idx >> 6, k = idx & 63;
    sH[k * SHS + er] = dist[(e0 + er) * 64 + k];
  }
  // W1 -> buf0
  {
    const float4* W14 = (const float4*)W1;
    float4* sW4 = (float4*)sW0;
    #pragma unroll
    for (int it = 0; it < 8; it++) sW4[t + it * 128] = W14[t + it * 128];
  }
  // edge_attr (stride 5 kills bank conflicts)
  #pragma unroll
  for (int idx = t; idx < 128 * 4; idx += 128) {
    int er = idx >> 2, c = idx & 3;
    sY[er * 5 + c] = edge_attr[(e0 + er) * 4 + c];
  }
  __syncthreads();

  // gather x = node_input[edge_dst] (L2-resident table)
  for (int idx = t; idx < 128 * 40; idx += 128) {
    int er = idx / 40, c = idx - er * 40;
    sX[er * 41 + c] = node_input[(long)sDst[er] * 40 + c];
  }

  // prefetch W2 chunk 0 into buf1 (overlaps GEMM1 compute)
  stage_chunk(t, sm + OFF_W1, 0);

  // ---- GEMM1 (4 edges/thread): h = SILU_NORM * silu((d @ W1)/8) ----
  u64 acc[4][8];
  #pragma unroll
  for (int ee = 0; ee < 4; ee++)
    #pragma unroll
    for (int j = 0; j < 8; j++) acc[ee][j] = 0ull;

  #pragma unroll 2
  for (int k = 0; k < 64; k++) {
    u64 d0 = dup2(sH[k * SHS + e]);
    u64 d1 = dup2(sH[k * SHS + e + 32]);
    u64 d2 = dup2(sH[k * SHS + e + 64]);
    u64 d3 = dup2(sH[k * SHS + e + 96]);
    const ulonglong2* wp = (const ulonglong2*)(sW0 + k * 64 + r * 16);
    ulonglong2 p0 = wp[0], p1 = wp[1], p2 = wp[2], p3 = wp[3];
    ffma2(acc[0][0], d0, p0.x);  ffma2(acc[0][1], d0, p0.y);
    ffma2(acc[0][2], d0, p1.x);  ffma2(acc[0][3], d0, p1.y);
    ffma2(acc[0][4], d0, p2.x);  ffma2(acc[0][5], d0, p2.y);
    ffma2(acc[0][6], d0, p3.x);  ffma2(acc[0][7], d0, p3.y);
    ffma2(acc[1][0], d1, p0.x);  ffma2(acc[1][1], d1, p0.y);
    ffma2(acc[1][2], d1, p1.x);  ffma2(acc[1][3], d1, p1.y);
    ffma2(acc[1][4], d1, p2.x);  ffma2(acc[1][5], d1, p2.y);
    ffma2(acc[1][6], d1, p3.x);  ffma2(acc[1][7], d1, p3.y);
    ffma2(acc[2][0], d2, p0.x);  ffma2(acc[2][1], d2, p0.y);
    ffma2(acc[2][2], d2, p1.x);  ffma2(acc[2][3], d2, p1.y);
    ffma2(acc[2][4], d2, p2.x);  ffma2(acc[2][5], d2, p2.y);
    ffma2(acc[2][6], d2, p3.x);  ffma2(acc[2][7], d2, p3.y);
    ffma2(acc[3][0], d3, p0.x);  ffma2(acc[3][1], d3, p0.y);
    ffma2(acc[3][2], d3, p1.x);  ffma2(acc[3][3], d3, p1.y);
    ffma2(acc[3][4], d3, p2.x);  ffma2(acc[3][5], d3, p2.y);
    ffma2(acc[3][6], d3, p3.x);  ffma2(acc[3][7], d3, p3.y);
  }
  __syncthreads();  // dist reads + W1 reads + chunk0 STS complete

  #pragma unroll
  for (int ee = 0; ee < 4; ee++) {
    #pragma unroll
    for (int j = 0; j < 8; j++) {
      float v0, v1;
      unpack2(acc[ee][j], v0, v1);
      v0 *= 0.125f;  v1 *= 0.125f;
      sH[(r * 16 + 2 * j + 0) * SHS + e + 32 * ee] = SILU_NORM * v0 / (1.0f + __expf(-v0));
      sH[(r * 16 + 2 * j + 1) * SHS + e + 32 * ee] = SILU_NORM * v1 / (1.0f + __expf(-v1));
    }
  }

  // per-edge scalars
  float y0_[4], y1x_[4], y1y_[4], y1z_[4];
  #pragma unroll
  for (int ee = 0; ee < 4; ee++) {
    int eidx = e + 32 * ee;
    y0_[ee]  = sY[eidx * 5 + 0];
    y1x_[ee] = sY[eidx * 5 + 1];
    y1y_[ee] = sY[eidx * 5 + 2];
    y1z_[ee] = sY[eidx * 5 + 3];
  }

  float acc0[4][4];
  float a1[4][6];
  #pragma unroll
  for (int ee = 0; ee < 4; ee++) {
    #pragma unroll
    for (int i = 0; i < 4; i++) acc0[ee][i] = 0.0f;
    #pragma unroll
    for (int i = 0; i < 6; i++) a1[ee][i] = 0.0f;
  }

  // ---- GEMM2 + tensor product, 9 double-buffered chunks ----
  do_chunk<0>(t, e, r, sm, y0_, y1x_, y1y_, y1z_, acc0, a1);
  do_chunk<1>(t, e, r, sm, y0_, y1x_, y1y_, y1z_, acc0, a1);
  do_chunk<2>(t, e, r, sm, y0_, y1x_, y1y_, y1z_, acc0, a1);
  do_chunk<3>(t, e, r, sm, y0_, y1x_, y1y_, y1z_, acc0, a1);
  do_chunk<4>(t, e, r, sm, y0_, y1x_, y1y_, y1z_, acc0, a1);
  do_chunk<5>(t, e, r, sm, y0_, y1x_, y1y_, y1z_, acc0, a1);
  do_chunk<6>(t, e, r, sm, y0_, y1x_, y1y_, y1z_, acc0, a1);
  do_chunk<7>(t, e, r, sm, y0_, y1x_, y1y_, y1z_, acc0, a1);
  do_chunk<8>(t, e, r, sm, y0_, y1x_, y1y_, y1z_, acc0, a1);

  // ---- scatter (disjoint columns across the 4 r-threads of an edge) ----
  #pragma unroll
  for (int ee = 0; ee < 4; ee++) {
    int base = sSrc[e + 32 * ee] * 40;
    #pragma unroll
    for (int gi = 0; gi < 4; gi++)
      atomicAdd(out + base + r + 4 * gi, S0F * acc0[ee][gi]);
    #pragma unroll
    for (int wp = 0; wp < 2; wp++)
      #pragma unroll
      for (int i = 0; i < 3; i++)
        atomicAdd(out + base + 16 + (2 * r + wp) * 3 + i, S0F * a1[ee][wp * 3 + i]);
  }
}

extern "C" void kernel_launch(void* const* d_in, const int* in_sizes, int n_in,
                              void* d_out, int out_size) {
  const float* node_input = (const float*)d_in[0];
  const int*   edge_src   = (const int*)d_in[1];
  const int*   edge_dst   = (const int*)d_in[2];
  const float* edge_attr  = (const float*)d_in[3];
  const float* dist       = (const float*)d_in[4];
  const float* W1         = (const float*)d_in[5];
  const float* W2         = (const float*)d_in[6];
  float* out = (float*)d_out;

  cudaFuncSetAttribute(fused_conv, cudaFuncAttributeMaxDynamicSharedMemorySize,
                       SMEM_BYTES);

  cudaMemsetAsync(out, 0, (size_t)out_size * sizeof(float));
  permute_w2<<<(WN + 127) / 128, 128>>>(W2);
  fused_conv<<<NBLK, 128, SMEM_BYTES>>>(node_input, edge_src, edge_dst,
                                        edge_attr, dist, W1, out);
}

// round 7
// speedup vs baseline: 1.8651x; 1.8651x over previous
#include <cuda_runtime.h>
#include <cuda_bf16.h>
#include <cstdint>

#define N_EDGES   400000
#define TE        128
#define NBLK      (N_EDGES / TE)   // 3125, exact
#define WN        576
#define C3F       0.5773502691896257f
#define S0F       0.006378879538497861f   // sqrt(1/24)/32
#define SILU_NORM 1.6791767923989418f

typedef uint32_t u32;

// ---- weight fragment tables (bf16 split, mma.sync fragment order) ---------
// layout: [chunk][kt][nt][lane][reg]; b0: k = kt*16 + (lane%4)*2 (+8 for reg1),
// n = nt*8 + lane/4; value = bf16x2(B[k][n], B[k+1][n]).
__device__ u32 g_B2h[9][4][8][32][2];
__device__ u32 g_B2l[9][4][8][32][2];
__device__ u32 g_B1h[4][8][32][2];
__device__ u32 g_B1l[4][8][32][2];

// permuted column map: mp = (g*4 + r)*16 + j  ->  original W2 column
__device__ __forceinline__ int w2col(int mp) {
  int j = mp & 15, gr = mp >> 4, g = gr >> 2, r = gr & 3;
  if (g < 4) return j * 16 + r + 4 * g;
  if (g < 6) return 448 + (j & 7) * 16 + r + 4 * ((g - 4) * 2 + (j >> 3));
  if (g < 8) return 256 + j * 8 + 2 * r + (g - 6);
  return 384 + (j & 7) * 8 + 2 * r + (j >> 3);
}

__device__ __forceinline__ void split_pack(float v0, float v1, u32 &hi, u32 &lo) {
  __nv_bfloat16 h0 = __float2bfloat16(v0), h1 = __float2bfloat16(v1);
  __nv_bfloat16 l0 = __float2bfloat16(v0 - __bfloat162float(h0));
  __nv_bfloat16 l1 = __float2bfloat16(v1 - __bfloat162float(h1));
  __nv_bfloat162 H; H.x = h0; H.y = h1;
  __nv_bfloat162 L; L.x = l0; L.y = l1;
  hi = *(u32*)&H;  lo = *(u32*)&L;
}

__global__ void prep_frags(const float* __restrict__ W1,
                           const float* __restrict__ W2) {
  int idx = blockIdx.x * blockDim.x + threadIdx.x;
  if (idx >= 10240) return;
  int lane = idx & 31;
  int nt = (idx >> 5) & 7;
  int kt = (idx >> 8) & 3;
  int C  = idx >> 10;                 // 0..8 = W2 chunks, 9 = W1
  int g = lane >> 2, c = lane & 3;
  int n = nt * 8 + g;
  #pragma unroll
  for (int r = 0; r < 2; r++) {
    int k = kt * 16 + c * 2 + r * 8;
    float v0, v1;
    if (C < 9) {
      int m = w2col(C * 64 + n);
      v0 = W2[k * WN + m];  v1 = W2[(k + 1) * WN + m];
    } else {
      v0 = W1[k * 64 + n];  v1 = W1[(k + 1) * 64 + n];
    }
    u32 hi, lo;  split_pack(v0, v1, hi, lo);
    if (C < 9) { g_B2h[C][kt][nt][lane][r] = hi;  g_B2l[C][kt][nt][lane][r] = lo; }
    else       { g_B1h[kt][nt][lane][r] = hi;     g_B1l[kt][nt][lane][r] = lo; }
  }
}

// ---- mma.sync bf16 ---------------------------------------------------------
__device__ __forceinline__ void mma16816(float (&d)[4], const u32 (&a)[4],
                                         const u32 (&b)[2]) {
  asm volatile(
      "mma.sync.aligned.m16n8k16.row.col.f32.bf16.bf16.f32 "
      "{%0,%1,%2,%3}, {%4,%5,%6,%7}, {%8,%9}, {%0,%1,%2,%3};"
      : "+f"(d[0]), "+f"(d[1]), "+f"(d[2]), "+f"(d[3])
      : "r"(a[0]), "r"(a[1]), "r"(a[2]), "r"(a[3]), "r"(b[0]), "r"(b[1]));
}

// ---- smem layout (float offsets) -------------------------------------------
#define OFF_D   0          // 128*68 f32 = 8704 (also h bf16 staging, stride 66)
#define OFF_B0  8704       // 4096 u32 (hi 2048 | lo 2048)
#define OFF_B1  12800      // 4096 u32
#define OFF_X   16896      // 128*41 f32
#define OFF_DST 22144      // 128 ints
#define SMEM_FLOATS 22272
#define SMEM_BYTES  (SMEM_FLOATS * 4)

__device__ __forceinline__ void stage(int t, u32* dst, const u32* sh, const u32* sl) {
  #pragma unroll
  for (int i = 0; i < 4; i++)
    ((uint4*)dst)[t + i * 128] = ((const uint4*)sh)[t + i * 128];
  #pragma unroll
  for (int i = 0; i < 4; i++)
    ((uint4*)(dst + 2048))[t + i * 128] = ((const uint4*)sl)[t + i * 128];
}

__device__ __forceinline__ void store_D(float* sD, int w, int g, int c,
                                        const float (&acc)[2][8][4]) {
  #pragma unroll
  for (int mt = 0; mt < 2; mt++) {
    int row0 = 32 * w + 16 * mt + g;
    #pragma unroll
    for (int nt = 0; nt < 8; nt++) {
      *(float2*)&sD[row0 * 68 + nt * 8 + 2 * c] =
          make_float2(acc[mt][nt][0], acc[mt][nt][1]);
      *(float2*)&sD[(row0 + 8) * 68 + nt * 8 + 2 * c] =
          make_float2(acc[mt][nt][2], acc[mt][nt][3]);
    }
  }
}

// ---- epilogue: tensor product for one 64-col chunk, one edge per lane ------
template <int G>
__device__ __forceinline__ void epi(const float* __restrict__ drow,
                                    const float* __restrict__ xr,
                                    float y0, float y1x, float y1y, float y1z,
                                    const float (&z4)[8],
                                    float (&o0)[16], float (&o1)[24]) {
  #pragma unroll
  for (int rr = 0; rr < 4; rr++) {
    float wv[16];
    #pragma unroll
    for (int i = 0; i < 4; i++)
      ((float4*)wv)[i] = *(const float4*)(drow + rr * 16 + 4 * i);

    if (G < 4) {
      float s = 0.f;
      #pragma unroll
      for (int j = 0; j < 16; j++) s += xr[j] * wv[j];
      o0[rr + 4 * G] += y0 * s;
    } else if (G < 6) {
      float sA = 0.f, sB = 0.f;
      #pragma unroll
      for (int u = 0; u < 8; u++) { sA += z4[u] * wv[u]; sB += z4[u] * wv[8 + u]; }
      o0[rr + 4 * (2 * (G - 4) + 0)] += C3F * sA;
      o0[rr + 4 * (2 * (G - 4) + 1)] += C3F * sB;
    } else if (G < 8) {
      float q = 0.f;
      #pragma unroll
      for (int j = 0; j < 16; j++) q += xr[j] * wv[j];
      const int ww = 2 * rr + (G - 6);
      o1[ww * 3 + 0] += q * y1x;  o1[ww * 3 + 1] += q * y1y;  o1[ww * 3 + 2] += q * y1z;
    } else {
      #pragma unroll
      for (int hf = 0; hf < 2; hf++) {
        float s0 = 0.f, s1 = 0.f, s2 = 0.f;
        #pragma unroll
        for (int u = 0; u < 8; u++) {
          float wu = wv[hf * 8 + u];
          s0 += xr[16 + 3 * u + 0] * wu;
          s1 += xr[16 + 3 * u + 1] * wu;
          s2 += xr[16 + 3 * u + 2] * wu;
        }
        const int ww = 2 * rr + hf;
        o1[ww * 3 + 0] += y0 * s0;  o1[ww * 3 + 1] += y0 * s1;  o1[ww * 3 + 2] += y0 * s2;
      }
    }
  }
}

// ---- main kernel ------------------------------------------------------------
__global__ __launch_bounds__(128, 2) void fused_conv(
    const float* __restrict__ node_input,
    const int*   __restrict__ edge_src,
    const int*   __restrict__ edge_dst,
    const float* __restrict__ edge_attr,
    const float* __restrict__ dist,
    float* __restrict__ out)
{
  extern __shared__ float sm[];
  float* sD  = sm + OFF_D;
  u32*   sB0 = (u32*)(sm + OFF_B0);
  u32*   sB1 = (u32*)(sm + OFF_B1);
  float* sX  = sm + OFF_X;
  int*   sDst = (int*)(sm + OFF_DST);

  const int t = threadIdx.x;
  const int lane = t & 31, w = t >> 5;
  const int g = lane >> 2, c = lane & 3;
  const long e0 = (long)blockIdx.x * TE;

  sDst[t] = edge_dst[e0 + t];
  const int my_src = edge_src[e0 + t];
  const float4 ya = ((const float4*)edge_attr)[e0 + t];

  // stage W1 frags -> B0, chunk0 -> B1
  stage(t, sB0, &g_B1h[0][0][0][0], &g_B1l[0][0][0][0]);
  stage(t, sB1, &g_B2h[0][0][0][0][0], &g_B2l[0][0][0][0][0]);
  __syncthreads();

  // gather node features (read only much later)
  for (int idx = t; idx < 128 * 40; idx += 128) {
    int er = idx / 40, cc = idx - er * 40;
    sX[er * 41 + cc] = node_input[(long)sDst[er] * 40 + cc];
  }

  // ---- GEMM1: D = dist @ W1 (bf16 split, 3 passes) ----
  {
    float acc[2][8][4];
    #pragma unroll
    for (int mt = 0; mt < 2; mt++)
      #pragma unroll
      for (int nt = 0; nt < 8; nt++)
        #pragma unroll
        for (int i = 0; i < 4; i++) acc[mt][nt][i] = 0.f;

    #pragma unroll
    for (int kt = 0; kt < 4; kt++) {
      u32 ah[2][4], al[2][4];
      #pragma unroll
      for (int mt = 0; mt < 2; mt++) {
        int row0 = 32 * w + 16 * mt + g;
        const float* dp = dist + (e0 + row0) * 64 + kt * 16 + 2 * c;
        float2 f0 = *(const float2*)(dp);
        float2 f1 = *(const float2*)(dp + 8 * 64);
        float2 f2 = *(const float2*)(dp + 8);
        float2 f3 = *(const float2*)(dp + 8 * 64 + 8);
        split_pack(f0.x, f0.y, ah[mt][0], al[mt][0]);
        split_pack(f1.x, f1.y, ah[mt][1], al[mt][1]);
        split_pack(f2.x, f2.y, ah[mt][2], al[mt][2]);
        split_pack(f3.x, f3.y, ah[mt][3], al[mt][3]);
      }
      #pragma unroll
      for (int nt = 0; nt < 8; nt++) {
        u32 bh[2], bl[2];
        *(uint2*)bh = *(const uint2*)&sB0[((kt * 8 + nt) * 32 + lane) * 2];
        *(uint2*)bl = *(const uint2*)&sB0[2048 + ((kt * 8 + nt) * 32 + lane) * 2];
        #pragma unroll
        for (int mt = 0; mt < 2; mt++) {
          mma16816(acc[mt][nt], ah[mt], bh);
          mma16816(acc[mt][nt], ah[mt], bl);
          mma16816(acc[mt][nt], al[mt], bh);
        }
      }
    }
    store_D(sD, w, g, c, acc);
  }
  __syncthreads();

  // silu on this lane's edge row
  float hv[64];
  #pragma unroll
  for (int i = 0; i < 16; i++) ((float4*)hv)[i] = *(const float4*)&sD[t * 68 + 4 * i];
  #pragma unroll
  for (int j = 0; j < 64; j++) {
    float v = hv[j] * 0.125f;
    hv[j] = SILU_NORM * v / (1.f + __expf(-v));
  }
  __syncthreads();   // all D reads done before overwrite

  // write h (bf16 split) into the D region: hi at byte 0, lo at +16896; stride 132B
  char* hb = (char*)sD;
  #pragma unroll
  for (int j = 0; j < 32; j++) {
    u32 hi, lo;  split_pack(hv[2 * j], hv[2 * j + 1], hi, lo);
    *(u32*)(hb + t * 132 + 4 * j) = hi;
    *(u32*)(hb + 16896 + t * 132 + 4 * j) = lo;
  }
  // stage chunk1 -> B0 (W1 reads complete)
  stage(t, sB0, &g_B2h[1][0][0][0][0], &g_B2l[1][0][0][0][0]);
  __syncthreads();

  // load persistent A fragments of h (hi/lo)
  u32 A2h[2][4][4], A2l[2][4][4];
  #pragma unroll
  for (int mt = 0; mt < 2; mt++) {
    int row0 = 32 * w + 16 * mt + g;
    #pragma unroll
    for (int kt = 0; kt < 4; kt++) {
      int cb = (kt * 16 + 2 * c) * 2;
      A2h[mt][kt][0] = *(const u32*)(hb + row0 * 132 + cb);
      A2h[mt][kt][1] = *(const u32*)(hb + (row0 + 8) * 132 + cb);
      A2h[mt][kt][2] = *(const u32*)(hb + row0 * 132 + cb + 16);
      A2h[mt][kt][3] = *(const u32*)(hb + (row0 + 8) * 132 + cb + 16);
      A2l[mt][kt][0] = *(const u32*)(hb + 16896 + row0 * 132 + cb);
      A2l[mt][kt][1] = *(const u32*)(hb + 16896 + (row0 + 8) * 132 + cb);
      A2l[mt][kt][2] = *(const u32*)(hb + 16896 + row0 * 132 + cb + 16);
      A2l[mt][kt][3] = *(const u32*)(hb + 16896 + (row0 + 8) * 132 + cb + 16);
    }
  }
  __syncthreads();   // A loads done -> D region reusable

  // per-lane epilogue inputs
  const float y0 = ya.x, y1x = ya.y, y1y = ya.z, y1z = ya.w;
  const float* xr = sX + t * 41;
  float z4[8];
  #pragma unroll
  for (int u = 0; u < 8; u++)
    z4[u] = xr[16 + 3 * u + 0] * y1x + xr[16 + 3 * u + 1] * y1y
          + xr[16 + 3 * u + 2] * y1z;

  float o0[16], o1[24];
  #pragma unroll
  for (int i = 0; i < 16; i++) o0[i] = 0.f;
  #pragma unroll
  for (int i = 0; i < 24; i++) o1[i] = 0.f;

  const float* drow = sD + t * 68;

  // ---- GEMM2 + tensor product, 9 chunks, double-buffered B ----
  #pragma unroll 1
  for (int G = 0; G < 9; G++) {
    u32* bcur = (G & 1) ? sB0 : sB1;   // chunk G lives here

    float acc[2][8][4];
    #pragma unroll
    for (int mt = 0; mt < 2; mt++)
      #pragma unroll
      for (int nt = 0; nt < 8; nt++)
        #pragma unroll
        for (int i = 0; i < 4; i++) acc[mt][nt][i] = 0.f;

    #pragma unroll
    for (int kt = 0; kt < 4; kt++)
      #pragma unroll
      for (int nt = 0; nt < 8; nt++) {
        u32 bh[2], bl[2];
        *(uint2*)bh = *(const uint2*)&bcur[((kt * 8 + nt) * 32 + lane) * 2];
        *(uint2*)bl = *(const uint2*)&bcur[2048 + ((kt * 8 + nt) * 32 + lane) * 2];
        #pragma unroll
        for (int mt = 0; mt < 2; mt++) {
          mma16816(acc[mt][nt], A2h[mt][kt], bh);
          mma16816(acc[mt][nt], A2h[mt][kt], bl);
          mma16816(acc[mt][nt], A2l[mt][kt], bh);
        }
      }

    store_D(sD, w, g, c, acc);
    __syncthreads();   // D visible; all mma reads of bcur done

    if (G <= 6)
      stage(t, bcur, &g_B2h[G + 2][0][0][0][0], &g_B2l[G + 2][0][0][0][0]);

    switch (G) {
      case 0: epi<0>(drow, xr, y0, y1x, y1y, y1z, z4, o0, o1); break;
      case 1: epi<1>(drow, xr, y0, y1x, y1y, y1z, z4, o0, o1); break;
      case 2: epi<2>(drow, xr, y0, y1x, y1y, y1z, z4, o0, o1); break;
      case 3: epi<3>(drow, xr, y0, y1x, y1y, y1z, z4, o0, o1); break;
      case 4: epi<4>(drow, xr, y0, y1x, y1y, y1z, z4, o0, o1); break;
      case 5: epi<5>(drow, xr, y0, y1x, y1y, y1z, z4, o0, o1); break;
      case 6: epi<6>(drow, xr, y0, y1x, y1y, y1z, z4, o0, o1); break;
      case 7: epi<7>(drow, xr, y0, y1x, y1y, y1z, z4, o0, o1); break;
      case 8: epi<8>(drow, xr, y0, y1x, y1y, y1z, z4, o0, o1); break;
    }
    __syncthreads();   // D reads done; staged buffer visible
  }

  // ---- scatter: 40 outputs for this lane's edge ----
  {
    const int base = my_src * 40;
    #pragma unroll
    for (int i = 0; i < 16; i++) atomicAdd(out + base + i, S0F * o0[i]);
    #pragma unroll
    for (int i = 0; i < 24; i++) atomicAdd(out + base + 16 + i, S0F * o1[i]);
  }
}

extern "C" void kernel_launch(void* const* d_in, const int* in_sizes, int n_in,
                              void* d_out, int out_size) {
  const float* node_input = (const float*)d_in[0];
  const int*   edge_src   = (const int*)d_in[1];
  const int*   edge_dst   = (const int*)d_in[2];
  const float* edge_attr  = (const float*)d_in[3];
  const float* dist       = (const float*)d_in[4];
  const float* W1         = (const float*)d_in[5];
  const float* W2         = (const float*)d_in[6];
  float* out = (float*)d_out;

  cudaFuncSetAttribute(fused_conv, cudaFuncAttributeMaxDynamicSharedMemorySize,
                       SMEM_BYTES);

  cudaMemsetAsync(out, 0, (size_t)out_size * sizeof(float));
  prep_frags<<<80, 128>>>(W1, W2);
  fused_conv<<<NBLK, 128, SMEM_BYTES>>>(node_input, edge_src, edge_dst,
                                        edge_attr, dist, out);
}

// round 8
// speedup vs baseline: 1.8720x; 1.0037x over previous
#include <cuda_runtime.h>
#include <cuda_bf16.h>
#include <cstdint>

#define N_EDGES   400000
#define TE        128
#define NBLK      (N_EDGES / TE)   // 3125, exact
#define WN        576
#define C3F       0.5773502691896257f
#define S0F       0.006378879538497861f   // sqrt(1/24)/32
#define SILU_NORM 1.6791767923989418f

typedef uint32_t u32;

// ---- weight fragment tables (bf16 split, mma.sync fragment order) ---------
// layout: [chunk][kt][nt][lane][reg]; b0: k = kt*16 + (lane%4)*2 (+8 for reg1),
// n = nt*8 + lane/4; value = bf16x2(B[k][n], B[k+1][n]).
__device__ u32 g_B2h[9][4][8][32][2];
__device__ u32 g_B2l[9][4][8][32][2];
__device__ u32 g_B1h[4][8][32][2];
__device__ u32 g_B1l[4][8][32][2];

// permuted column map: mp = (g*4 + r)*16 + j  ->  original W2 column
__device__ __forceinline__ int w2col(int mp) {
  int j = mp & 15, gr = mp >> 4, g = gr >> 2, r = gr & 3;
  if (g < 4) return j * 16 + r + 4 * g;
  if (g < 6) return 448 + (j & 7) * 16 + r + 4 * ((g - 4) * 2 + (j >> 3));
  if (g < 8) return 256 + j * 8 + 2 * r + (g - 6);
  return 384 + (j & 7) * 8 + 2 * r + (j >> 3);
}

__device__ __forceinline__ void split_pack(float v0, float v1, u32 &hi, u32 &lo) {
  __nv_bfloat16 h0 = __float2bfloat16(v0), h1 = __float2bfloat16(v1);
  __nv_bfloat16 l0 = __float2bfloat16(v0 - __bfloat162float(h0));
  __nv_bfloat16 l1 = __float2bfloat16(v1 - __bfloat162float(h1));
  __nv_bfloat162 H; H.x = h0; H.y = h1;
  __nv_bfloat162 L; L.x = l0; L.y = l1;
  hi = *(u32*)&H;  lo = *(u32*)&L;
}

__global__ void prep_frags(const float* __restrict__ W1,
                           const float* __restrict__ W2) {
  int idx = blockIdx.x * blockDim.x + threadIdx.x;
  if (idx >= 10240) return;
  int lane = idx & 31;
  int nt = (idx >> 5) & 7;
  int kt = (idx >> 8) & 3;
  int C  = idx >> 10;                 // 0..8 = W2 chunks, 9 = W1
  int g = lane >> 2, c = lane & 3;
  int n = nt * 8 + g;
  #pragma unroll
  for (int r = 0; r < 2; r++) {
    int k = kt * 16 + c * 2 + r * 8;
    float v0, v1;
    if (C < 9) {
      int m = w2col(C * 64 + n);
      v0 = W2[k * WN + m];  v1 = W2[(k + 1) * WN + m];
    } else {
      v0 = W1[k * 64 + n];  v1 = W1[(k + 1) * 64 + n];
    }
    u32 hi, lo;  split_pack(v0, v1, hi, lo);
    if (C < 9) { g_B2h[C][kt][nt][lane][r] = hi;  g_B2l[C][kt][nt][lane][r] = lo; }
    else       { g_B1h[kt][nt][lane][r] = hi;     g_B1l[kt][nt][lane][r] = lo; }
  }
}

// ---- mma.sync bf16 ---------------------------------------------------------
__device__ __forceinline__ void mma16816(float (&d)[4], const u32 (&a)[4],
                                         const u32 (&b)[2]) {
  asm volatile(
      "mma.sync.aligned.m16n8k16.row.col.f32.bf16.bf16.f32 "
      "{%0,%1,%2,%3}, {%4,%5,%6,%7}, {%8,%9}, {%0,%1,%2,%3};"
      : "+f"(d[0]), "+f"(d[1]), "+f"(d[2]), "+f"(d[3])
      : "r"(a[0]), "r"(a[1]), "r"(a[2]), "r"(a[3]), "r"(b[0]), "r"(b[1]));
}

// ---- smem layout (float offsets) -------------------------------------------
#define OFF_D   0          // 128*68 f32 = 8704 f (D tiles; also warp-private h stage)
#define OFF_B0  8704       // 4096 u32 (hi 2048 | lo 2048)
#define OFF_B1  12800      // 4096 u32
#define OFF_X   16896      // 128*41 f32
#define OFF_DST 22144      // 128 ints
#define SMEM_FLOATS 22272
#define SMEM_BYTES  (SMEM_FLOATS * 4)

__device__ __forceinline__ void stage(int t, u32* dst, const u32* sh, const u32* sl) {
  #pragma unroll
  for (int i = 0; i < 4; i++)
    ((uint4*)dst)[t + i * 128] = ((const uint4*)sh)[t + i * 128];
  #pragma unroll
  for (int i = 0; i < 4; i++)
    ((uint4*)(dst + 2048))[t + i * 128] = ((const uint4*)sl)[t + i * 128];
}

__device__ __forceinline__ void store_D(float* sD, int w, int g, int c,
                                        const float (&acc)[2][8][4]) {
  #pragma unroll
  for (int mt = 0; mt < 2; mt++) {
    int row0 = 32 * w + 16 * mt + g;
    #pragma unroll
    for (int nt = 0; nt < 8; nt++) {
      *(float2*)&sD[row0 * 68 + nt * 8 + 2 * c] =
          make_float2(acc[mt][nt][0], acc[mt][nt][1]);
      *(float2*)&sD[(row0 + 8) * 68 + nt * 8 + 2 * c] =
          make_float2(acc[mt][nt][2], acc[mt][nt][3]);
    }
  }
}

// ---- epilogue: tensor product for one 64-col chunk, one edge per lane ------
template <int G>
__device__ __forceinline__ void epi(const float* __restrict__ drow,
                                    const float* __restrict__ xr,
                                    float y0, float y1x, float y1y, float y1z,
                                    const float (&z4)[8],
                                    float (&o0)[16], float (&o1)[24]) {
  #pragma unroll
  for (int rr = 0; rr < 4; rr++) {
    float wv[16];
    #pragma unroll
    for (int i = 0; i < 4; i++)
      ((float4*)wv)[i] = *(const float4*)(drow + rr * 16 + 4 * i);

    if (G < 4) {
      float s = 0.f;
      #pragma unroll
      for (int j = 0; j < 16; j++) s += xr[j] * wv[j];
      o0[rr + 4 * G] += y0 * s;
    } else if (G < 6) {
      float sA = 0.f, sB = 0.f;
      #pragma unroll
      for (int u = 0; u < 8; u++) { sA += z4[u] * wv[u]; sB += z4[u] * wv[8 + u]; }
      o0[rr + 4 * (2 * (G - 4) + 0)] += C3F * sA;
      o0[rr + 4 * (2 * (G - 4) + 1)] += C3F * sB;
    } else if (G < 8) {
      float q = 0.f;
      #pragma unroll
      for (int j = 0; j < 16; j++) q += xr[j] * wv[j];
      const int ww = 2 * rr + (G - 6);
      o1[ww * 3 + 0] += q * y1x;  o1[ww * 3 + 1] += q * y1y;  o1[ww * 3 + 2] += q * y1z;
    } else {
      #pragma unroll
      for (int hf = 0; hf < 2; hf++) {
        float s0 = 0.f, s1 = 0.f, s2 = 0.f;
        #pragma unroll
        for (int u = 0; u < 8; u++) {
          float wu = wv[hf * 8 + u];
          s0 += xr[16 + 3 * u + 0] * wu;
          s1 += xr[16 + 3 * u + 1] * wu;
          s2 += xr[16 + 3 * u + 2] * wu;
        }
        const int ww = 2 * rr + hf;
        o1[ww * 3 + 0] += y0 * s0;  o1[ww * 3 + 1] += y0 * s1;  o1[ww * 3 + 2] += y0 * s2;
      }
    }
  }
}

// ---- main kernel ------------------------------------------------------------
__global__ __launch_bounds__(128, 2) void fused_conv(
    const float* __restrict__ node_input,
    const int*   __restrict__ edge_src,
    const int*   __restrict__ edge_dst,
    const float* __restrict__ edge_attr,
    const float* __restrict__ dist,
    float* __restrict__ out)
{
  extern __shared__ float sm[];
  float* sD  = sm + OFF_D;
  u32*   sB0 = (u32*)(sm + OFF_B0);
  u32*   sB1 = (u32*)(sm + OFF_B1);
  float* sX  = sm + OFF_X;
  int*   sDst = (int*)(sm + OFF_DST);

  const int t = threadIdx.x;
  const int lane = t & 31, w = t >> 5;
  const int g = lane >> 2, c = lane & 3;
  const long e0 = (long)blockIdx.x * TE;

  sDst[t] = edge_dst[e0 + t];
  const int my_src = edge_src[e0 + t];
  const float4 ya = ((const float4*)edge_attr)[e0 + t];

  // stage W1 frags -> B0, chunk0 -> B1
  stage(t, sB0, &g_B1h[0][0][0][0], &g_B1l[0][0][0][0]);
  stage(t, sB1, &g_B2h[0][0][0][0][0], &g_B2l[0][0][0][0][0]);
  __syncthreads();   // sDst + B0/B1 visible

  // gather node features (consumed in epi, after the GEMM1 barrier)
  for (int idx = t; idx < 128 * 40; idx += 128) {
    int er = idx / 40, cc = idx - er * 40;
    sX[er * 41 + cc] = node_input[(long)sDst[er] * 40 + cc];
  }

  // ---- GEMM1: D = dist @ W1 (bf16 split, 3 passes) ----
  {
    float acc[2][8][4];
    #pragma unroll
    for (int mt = 0; mt < 2; mt++)
      #pragma unroll
      for (int nt = 0; nt < 8; nt++)
        #pragma unroll
        for (int i = 0; i < 4; i++) acc[mt][nt][i] = 0.f;

    #pragma unroll
    for (int kt = 0; kt < 4; kt++) {
      u32 ah[2][4], al[2][4];
      #pragma unroll
      for (int mt = 0; mt < 2; mt++) {
        int row0 = 32 * w + 16 * mt + g;
        const float* dp = dist + (e0 + row0) * 64 + kt * 16 + 2 * c;
        float2 f0 = *(const float2*)(dp);
        float2 f1 = *(const float2*)(dp + 8 * 64);
        float2 f2 = *(const float2*)(dp + 8);
        float2 f3 = *(const float2*)(dp + 8 * 64 + 8);
        split_pack(f0.x, f0.y, ah[mt][0], al[mt][0]);
        split_pack(f1.x, f1.y, ah[mt][1], al[mt][1]);
        split_pack(f2.x, f2.y, ah[mt][2], al[mt][2]);
        split_pack(f3.x, f3.y, ah[mt][3], al[mt][3]);
      }
      #pragma unroll
      for (int nt = 0; nt < 8; nt++) {
        u32 bh[2], bl[2];
        *(uint2*)bh = *(const uint2*)&sB0[((kt * 8 + nt) * 32 + lane) * 2];
        *(uint2*)bl = *(const uint2*)&sB0[2048 + ((kt * 8 + nt) * 32 + lane) * 2];
        #pragma unroll
        for (int mt = 0; mt < 2; mt++) {
          mma16816(acc[mt][nt], ah[mt], bh);
          mma16816(acc[mt][nt], ah[mt], bl);
          mma16816(acc[mt][nt], al[mt], bh);
        }
      }
    }
    __syncthreads();   // all warps done reading B0 (W1)
    stage(t, sB0, &g_B2h[1][0][0][0][0], &g_B2l[1][0][0][0][0]);  // chunk1 -> B0

    store_D(sD, w, g, c, acc);   // warp-private rows
    __syncwarp();
  }

  // silu on this lane's edge row (warp-private D slice)
  float hv[64];
  #pragma unroll
  for (int i = 0; i < 16; i++) ((float4*)hv)[i] = *(const float4*)&sD[t * 68 + 4 * i];
  #pragma unroll
  for (int j = 0; j < 64; j++) {
    float v = hv[j] * 0.125f;
    hv[j] = SILU_NORM * v / (1.f + __expf(-v));
  }
  __syncwarp();   // warp's D reads done before overwrite

  // write h (bf16 split) into the warp's own D slice:
  //   hi at warpbase + lane*132, lo at warpbase + 4224 + lane*132 (132B row stride)
  char* hwarp = (char*)sD + 8704 * w;
  #pragma unroll
  for (int j = 0; j < 32; j++) {
    u32 hi, lo;  split_pack(hv[2 * j], hv[2 * j + 1], hi, lo);
    *(u32*)(hwarp + lane * 132 + 4 * j) = hi;
    *(u32*)(hwarp + 4224 + lane * 132 + 4 * j) = lo;
  }
  __syncwarp();

  // load persistent A fragments of h (hi/lo) — all within this warp's slice
  u32 A2h[2][4][4], A2l[2][4][4];
  #pragma unroll
  for (int mt = 0; mt < 2; mt++) {
    int rl = 16 * mt + g;   // local row within warp slice
    #pragma unroll
    for (int kt = 0; kt < 4; kt++) {
      int cb = (kt * 16 + 2 * c) * 2;
      A2h[mt][kt][0] = *(const u32*)(hwarp + rl * 132 + cb);
      A2h[mt][kt][1] = *(const u32*)(hwarp + (rl + 8) * 132 + cb);
      A2h[mt][kt][2] = *(const u32*)(hwarp + rl * 132 + cb + 16);
      A2h[mt][kt][3] = *(const u32*)(hwarp + (rl + 8) * 132 + cb + 16);
      A2l[mt][kt][0] = *(const u32*)(hwarp + 4224 + rl * 132 + cb);
      A2l[mt][kt][1] = *(const u32*)(hwarp + 4224 + (rl + 8) * 132 + cb);
      A2l[mt][kt][2] = *(const u32*)(hwarp + 4224 + rl * 132 + cb + 16);
      A2l[mt][kt][3] = *(const u32*)(hwarp + 4224 + (rl + 8) * 132 + cb + 16);
    }
  }
  __syncwarp();   // A frag loads done -> warp slice reusable as D

  // per-lane epilogue inputs
  const float y0 = ya.x, y1x = ya.y, y1y = ya.z, y1z = ya.w;
  const float* xr = sX + t * 41;
  float z4[8];
  #pragma unroll
  for (int u = 0; u < 8; u++)
    z4[u] = xr[16 + 3 * u + 0] * y1x + xr[16 + 3 * u + 1] * y1y
          + xr[16 + 3 * u + 2] * y1z;

  float o0[16], o1[24];
  #pragma unroll
  for (int i = 0; i < 16; i++) o0[i] = 0.f;
  #pragma unroll
  for (int i = 0; i < 24; i++) o1[i] = 0.f;

  const float* drow = sD + t * 68;

  // ---- GEMM2 + tensor product, 9 chunks ----
  // One CTA barrier per chunk (right after MMA); D round-trip is warp-private.
  #pragma unroll 1
  for (int G = 0; G < 9; G++) {
    u32* bcur = (G & 1) ? sB0 : sB1;   // chunk G lives here

    float acc[2][8][4];
    #pragma unroll
    for (int mt = 0; mt < 2; mt++)
      #pragma unroll
      for (int nt = 0; nt < 8; nt++)
        #pragma unroll
        for (int i = 0; i < 4; i++) acc[mt][nt][i] = 0.f;

    #pragma unroll
    for (int kt = 0; kt < 4; kt++)
      #pragma unroll
      for (int nt = 0; nt < 8; nt++) {
        u32 bh[2], bl[2];
        *(uint2*)bh = *(const uint2*)&bcur[((kt * 8 + nt) * 32 + lane) * 2];
        *(uint2*)bl = *(const uint2*)&bcur[2048 + ((kt * 8 + nt) * 32 + lane) * 2];
        #pragma unroll
        for (int mt = 0; mt < 2; mt++) {
          mma16816(acc[mt][nt], A2h[mt][kt], bh);
          mma16816(acc[mt][nt], A2h[mt][kt], bl);
          mma16816(acc[mt][nt], A2l[mt][kt], bh);
        }
      }

    __syncthreads();   // all warps done reading bcur; prior stage visible to next MMA
    if (G <= 6)
      stage(t, bcur, &g_B2h[G + 2][0][0][0][0], &g_B2l[G + 2][0][0][0][0]);

    store_D(sD, w, g, c, acc);   // warp-private
    __syncwarp();

    switch (G) {
      case 0: epi<0>(drow, xr, y0, y1x, y1y, y1z, z4, o0, o1); break;
      case 1: epi<1>(drow, xr, y0, y1x, y1y, y1z, z4, o0, o1); break;
      case 2: epi<2>(drow, xr, y0, y1x, y1y, y1z, z4, o0, o1); break;
      case 3: epi<3>(drow, xr, y0, y1x, y1y, y1z, z4, o0, o1); break;
      case 4: epi<4>(drow, xr, y0, y1x, y1y, y1z, z4, o0, o1); break;
      case 5: epi<5>(drow, xr, y0, y1x, y1y, y1z, z4, o0, o1); break;
      case 6: epi<6>(drow, xr, y0, y1x, y1y, y1z, z4, o0, o1); break;
      case 7: epi<7>(drow, xr, y0, y1x, y1y, y1z, z4, o0, o1); break;
      case 8: epi<8>(drow, xr, y0, y1x, y1y, y1z, z4, o0, o1); break;
    }
    __syncwarp();   // warp's D reads done before next chunk's store_D
  }

  // ---- scatter: 40 outputs for this lane's edge ----
  {
    const int base = my_src * 40;
    #pragma unroll
    for (int i = 0; i < 16; i++) atomicAdd(out + base + i, S0F * o0[i]);
    #pragma unroll
    for (int i = 0; i < 24; i++) atomicAdd(out + base + 16 + i, S0F * o1[i]);
  }
}

extern "C" void kernel_launch(void* const* d_in, const int* in_sizes, int n_in,
                              void* d_out, int out_size) {
  const float* node_input = (const float*)d_in[0];
  const int*   edge_src   = (const int*)d_in[1];
  const int*   edge_dst   = (const int*)d_in[2];
  const float* edge_attr  = (const float*)d_in[3];
  const float* dist       = (const float*)d_in[4];
  const float* W1         = (const float*)d_in[5];
  const float* W2         = (const float*)d_in[6];
  float* out = (float*)d_out;

  cudaFuncSetAttribute(fused_conv, cudaFuncAttributeMaxDynamicSharedMemorySize,
                       SMEM_BYTES);

  cudaMemsetAsync(out, 0, (size_t)out_size * sizeof(float));
  prep_frags<<<80, 128>>>(W1, W2);
  fused_conv<<<NBLK, 128, SMEM_BYTES>>>(node_input, edge_src, edge_dst,
                                        edge_attr, dist, out);
}

// round 9
// speedup vs baseline: 2.2913x; 1.2240x over previous
#include <cuda_runtime.h>
#include <cuda_bf16.h>
#include <cstdint>

#define N_EDGES   400000
#define TE        128
#define NBLK      (N_EDGES / TE)   // 3125, exact
#define WN        576
#define C3F       0.5773502691896257f
#define S0F       0.006378879538497861f   // sqrt(1/24)/32
#define SILU_NORM 1.6791767923989418f

typedef uint32_t u32;

// ---- weight fragment tables (bf16 split, mma.sync fragment order) ---------
__device__ u32 g_B2h[9][4][8][32][2];
__device__ u32 g_B2l[9][4][8][32][2];
__device__ u32 g_B1h[4][8][32][2];
__device__ u32 g_B1l[4][8][32][2];

__device__ __forceinline__ int w2col(int mp) {
  int j = mp & 15, gr = mp >> 4, g = gr >> 2, r = gr & 3;
  if (g < 4) return j * 16 + r + 4 * g;
  if (g < 6) return 448 + (j & 7) * 16 + r + 4 * ((g - 4) * 2 + (j >> 3));
  if (g < 8) return 256 + j * 8 + 2 * r + (g - 6);
  return 384 + (j & 7) * 8 + 2 * r + (j >> 3);
}

__device__ __forceinline__ void split_pack(float v0, float v1, u32 &hi, u32 &lo) {
  __nv_bfloat16 h0 = __float2bfloat16(v0), h1 = __float2bfloat16(v1);
  __nv_bfloat16 l0 = __float2bfloat16(v0 - __bfloat162float(h0));
  __nv_bfloat16 l1 = __float2bfloat16(v1 - __bfloat162float(h1));
  __nv_bfloat162 H; H.x = h0; H.y = h1;
  __nv_bfloat162 L; L.x = l0; L.y = l1;
  hi = *(u32*)&H;  lo = *(u32*)&L;
}

__global__ void prep_frags(const float* __restrict__ W1,
                           const float* __restrict__ W2) {
  int idx = blockIdx.x * blockDim.x + threadIdx.x;
  if (idx >= 10240) return;
  int lane = idx & 31;
  int nt = (idx >> 5) & 7;
  int kt = (idx >> 8) & 3;
  int C  = idx >> 10;                 // 0..8 = W2 chunks, 9 = W1
  int g = lane >> 2, c = lane & 3;
  int n = nt * 8 + g;
  #pragma unroll
  for (int r = 0; r < 2; r++) {
    int k = kt * 16 + c * 2 + r * 8;
    float v0, v1;
    if (C < 9) {
      int m = w2col(C * 64 + n);
      v0 = W2[k * WN + m];  v1 = W2[(k + 1) * WN + m];
    } else {
      v0 = W1[k * 64 + n];  v1 = W1[(k + 1) * 64 + n];
    }
    u32 hi, lo;  split_pack(v0, v1, hi, lo);
    if (C < 9) { g_B2h[C][kt][nt][lane][r] = hi;  g_B2l[C][kt][nt][lane][r] = lo; }
    else       { g_B1h[kt][nt][lane][r] = hi;     g_B1l[kt][nt][lane][r] = lo; }
  }
}

__device__ __forceinline__ void mma16816(float (&d)[4], const u32 (&a)[4],
                                         const u32 (&b)[2]) {
  asm volatile(
      "mma.sync.aligned.m16n8k16.row.col.f32.bf16.bf16.f32 "
      "{%0,%1,%2,%3}, {%4,%5,%6,%7}, {%8,%9}, {%0,%1,%2,%3};"
      : "+f"(d[0]), "+f"(d[1]), "+f"(d[2]), "+f"(d[3])
      : "r"(a[0]), "r"(a[1]), "r"(a[2]), "r"(a[3]), "r"(b[0]), "r"(b[1]));
}

// ---- smem layout (float offsets) -------------------------------------------
#define OFF_D   0          // 128*68 f32 (D tiles; also warp-private h stage)
#define OFF_B0  8704       // 4096 u32 (hi 2048 | lo 2048)
#define OFF_B1  12800      // 4096 u32
#define SMEM_FLOATS 16896
#define SMEM_BYTES  (SMEM_FLOATS * 4)   // 67584 B -> 3 CTAs/SM

__device__ __forceinline__ void stage(int t, u32* dst, const u32* sh, const u32* sl) {
  #pragma unroll
  for (int i = 0; i < 4; i++)
    ((uint4*)dst)[t + i * 128] = ((const uint4*)sh)[t + i * 128];
  #pragma unroll
  for (int i = 0; i < 4; i++)
    ((uint4*)(dst + 2048))[t + i * 128] = ((const uint4*)sl)[t + i * 128];
}

// store one nt-half (4 n-tiles) of the warp's D tile
__device__ __forceinline__ void store_D_half(float* sD, int w, int g, int c, int h,
                                             const float (&acc)[2][4][4]) {
  #pragma unroll
  for (int mt = 0; mt < 2; mt++) {
    int row0 = 32 * w + 16 * mt + g;
    #pragma unroll
    for (int q = 0; q < 4; q++) {
      int nc = (4 * h + q) * 8 + 2 * c;
      *(float2*)&sD[row0 * 68 + nc] = make_float2(acc[mt][q][0], acc[mt][q][1]);
      *(float2*)&sD[(row0 + 8) * 68 + nc] = make_float2(acc[mt][q][2], acc[mt][q][3]);
    }
  }
}

// ---- epilogue: tensor product for one 64-col chunk, one edge per lane ------
template <int G>
__device__ __forceinline__ void epi(const float* __restrict__ drow,
                                    const float (&x0)[16],
                                    const float* __restrict__ xg,
                                    float y0, float y1x, float y1y, float y1z,
                                    const float (&z4)[8],
                                    float (&o0)[16], float (&o1)[24]) {
  #pragma unroll
  for (int rr = 0; rr < 4; rr++) {
    float wv[16];
    #pragma unroll
    for (int i = 0; i < 4; i++)
      ((float4*)wv)[i] = *(const float4*)(drow + rr * 16 + 4 * i);

    if (G < 4) {
      float s = 0.f;
      #pragma unroll
      for (int j = 0; j < 16; j++) s += x0[j] * wv[j];
      o0[rr + 4 * G] += y0 * s;
    } else if (G < 6) {
      float sA = 0.f, sB = 0.f;
      #pragma unroll
      for (int u = 0; u < 8; u++) { sA += z4[u] * wv[u]; sB += z4[u] * wv[8 + u]; }
      o0[rr + 4 * (2 * (G - 4) + 0)] += C3F * sA;
      o0[rr + 4 * (2 * (G - 4) + 1)] += C3F * sB;
    } else if (G < 8) {
      float q = 0.f;
      #pragma unroll
      for (int j = 0; j < 16; j++) q += x0[j] * wv[j];
      const int ww = 2 * rr + (G - 6);
      o1[ww * 3 + 0] += q * y1x;  o1[ww * 3 + 1] += q * y1y;  o1[ww * 3 + 2] += q * y1z;
    } else {
      // x1 reloaded from global (L1-resident; only for this final chunk)
      #pragma unroll
      for (int hf = 0; hf < 2; hf++) {
        float s0 = 0.f, s1 = 0.f, s2 = 0.f;
        #pragma unroll
        for (int u = 0; u < 8; u++) {
          float wu = wv[hf * 8 + u];
          s0 += xg[16 + 3 * u + 0] * wu;
          s1 += xg[16 + 3 * u + 1] * wu;
          s2 += xg[16 + 3 * u + 2] * wu;
        }
        const int ww = 2 * rr + hf;
        o1[ww * 3 + 0] += y0 * s0;  o1[ww * 3 + 1] += y0 * s1;  o1[ww * 3 + 2] += y0 * s2;
      }
    }
  }
}

// ---- main kernel ------------------------------------------------------------
__global__ __launch_bounds__(128, 3) void fused_conv(
    const float* __restrict__ node_input,
    const int*   __restrict__ edge_src,
    const int*   __restrict__ edge_dst,
    const float* __restrict__ edge_attr,
    const float* __restrict__ dist,
    float* __restrict__ out)
{
  extern __shared__ float sm[];
  float* sD  = sm + OFF_D;
  u32*   sB0 = (u32*)(sm + OFF_B0);
  u32*   sB1 = (u32*)(sm + OFF_B1);

  const int t = threadIdx.x;
  const int lane = t & 31, w = t >> 5;
  const int g = lane >> 2, c = lane & 3;
  const long e0 = (long)blockIdx.x * TE;

  const int my_src = edge_src[e0 + t];
  const int my_dst = edge_dst[e0 + t];
  const float4 ya = ((const float4*)edge_attr)[e0 + t];
  const float y0 = ya.x, y1x = ya.y, y1y = ya.z, y1z = ya.w;
  const float* xg = node_input + (long)my_dst * 40;

  // per-lane node features: x0 in regs, z4 computed once
  float x0[16];
  #pragma unroll
  for (int i = 0; i < 4; i++) ((float4*)x0)[i] = *(const float4*)(xg + 4 * i);
  float z4[8];
  #pragma unroll
  for (int u = 0; u < 8; u++)
    z4[u] = xg[16 + 3 * u + 0] * y1x + xg[16 + 3 * u + 1] * y1y
          + xg[16 + 3 * u + 2] * y1z;

  // stage W1 frags -> B0, chunk0 -> B1
  stage(t, sB0, &g_B1h[0][0][0][0], &g_B1l[0][0][0][0]);
  stage(t, sB1, &g_B2h[0][0][0][0][0], &g_B2l[0][0][0][0][0]);
  __syncthreads();

  // ---- GEMM1: D = dist @ W1 (bf16 split, 3 passes) ----
  {
    float acc[2][8][4];
    #pragma unroll
    for (int mt = 0; mt < 2; mt++)
      #pragma unroll
      for (int nt = 0; nt < 8; nt++)
        #pragma unroll
        for (int i = 0; i < 4; i++) acc[mt][nt][i] = 0.f;

    #pragma unroll
    for (int kt = 0; kt < 4; kt++) {
      u32 ah[2][4], al[2][4];
      #pragma unroll
      for (int mt = 0; mt < 2; mt++) {
        int row0 = 32 * w + 16 * mt + g;
        const float* dp = dist + (e0 + row0) * 64 + kt * 16 + 2 * c;
        float2 f0 = *(const float2*)(dp);
        float2 f1 = *(const float2*)(dp + 8 * 64);
        float2 f2 = *(const float2*)(dp + 8);
        float2 f3 = *(const float2*)(dp + 8 * 64 + 8);
        split_pack(f0.x, f0.y, ah[mt][0], al[mt][0]);
        split_pack(f1.x, f1.y, ah[mt][1], al[mt][1]);
        split_pack(f2.x, f2.y, ah[mt][2], al[mt][2]);
        split_pack(f3.x, f3.y, ah[mt][3], al[mt][3]);
      }
      #pragma unroll
      for (int nt = 0; nt < 8; nt++) {
        u32 bh[2], bl[2];
        *(uint2*)bh = *(const uint2*)&sB0[((kt * 8 + nt) * 32 + lane) * 2];
        *(uint2*)bl = *(const uint2*)&sB0[2048 + ((kt * 8 + nt) * 32 + lane) * 2];
        #pragma unroll
        for (int mt = 0; mt < 2; mt++) {
          mma16816(acc[mt][nt], ah[mt], bh);
          mma16816(acc[mt][nt], ah[mt], bl);
          mma16816(acc[mt][nt], al[mt], bh);
        }
      }
    }
    __syncthreads();   // all warps done reading B0 (W1)
    stage(t, sB0, &g_B2h[1][0][0][0][0], &g_B2l[1][0][0][0][0]);  // chunk1 -> B0

    #pragma unroll
    for (int mt = 0; mt < 2; mt++) {
      int row0 = 32 * w + 16 * mt + g;
      #pragma unroll
      for (int nt = 0; nt < 8; nt++) {
        *(float2*)&sD[row0 * 68 + nt * 8 + 2 * c] =
            make_float2(acc[mt][nt][0], acc[mt][nt][1]);
        *(float2*)&sD[(row0 + 8) * 68 + nt * 8 + 2 * c] =
            make_float2(acc[mt][nt][2], acc[mt][nt][3]);
      }
    }
    __syncwarp();
  }

  // silu on this lane's edge row (warp-private D slice)
  {
    float hv[64];
    #pragma unroll
    for (int i = 0; i < 16; i++)
      ((float4*)hv)[i] = *(const float4*)&sD[t * 68 + 4 * i];
    #pragma unroll
    for (int j = 0; j < 64; j++) {
      float v = hv[j] * 0.125f;
      hv[j] = SILU_NORM * v / (1.f + __expf(-v));
    }
    __syncwarp();   // warp's D reads done before overwrite

    // write h (bf16 split) into the warp's own D slice (132B row stride)
    char* hwarp = (char*)sD + 8704 * w;
    #pragma unroll
    for (int j = 0; j < 32; j++) {
      u32 hi, lo;  split_pack(hv[2 * j], hv[2 * j + 1], hi, lo);
      *(u32*)(hwarp + lane * 132 + 4 * j) = hi;
      *(u32*)(hwarp + 4224 + lane * 132 + 4 * j) = lo;
    }
    __syncwarp();
  }

  // load persistent A fragments of h (hi/lo) — within this warp's slice
  u32 A2h[2][4][4], A2l[2][4][4];
  {
    char* hwarp = (char*)sD + 8704 * w;
    #pragma unroll
    for (int mt = 0; mt < 2; mt++) {
      int rl = 16 * mt + g;
      #pragma unroll
      for (int kt = 0; kt < 4; kt++) {
        int cb = (kt * 16 + 2 * c) * 2;
        A2h[mt][kt][0] = *(const u32*)(hwarp + rl * 132 + cb);
        A2h[mt][kt][1] = *(const u32*)(hwarp + (rl + 8) * 132 + cb);
        A2h[mt][kt][2] = *(const u32*)(hwarp + rl * 132 + cb + 16);
        A2h[mt][kt][3] = *(const u32*)(hwarp + (rl + 8) * 132 + cb + 16);
        A2l[mt][kt][0] = *(const u32*)(hwarp + 4224 + rl * 132 + cb);
        A2l[mt][kt][1] = *(const u32*)(hwarp + 4224 + (rl + 8) * 132 + cb);
        A2l[mt][kt][2] = *(const u32*)(hwarp + 4224 + rl * 132 + cb + 16);
        A2l[mt][kt][3] = *(const u32*)(hwarp + 4224 + (rl + 8) * 132 + cb + 16);
      }
    }
    __syncwarp();   // A frag loads done -> warp slice reusable as D
  }

  float o0[16], o1[24];
  #pragma unroll
  for (int i = 0; i < 16; i++) o0[i] = 0.f;
  #pragma unroll
  for (int i = 0; i < 24; i++) o1[i] = 0.f;

  const float* drow = sD + t * 68;

  // ---- GEMM2 + tensor product, 9 chunks (nt split in two halves) ----
  #pragma unroll 1
  for (int G = 0; G < 9; G++) {
    u32* bcur = (G & 1) ? sB0 : sB1;   // chunk G lives here

    #pragma unroll
    for (int h = 0; h < 2; h++) {
      float acc[2][4][4];
      #pragma unroll
      for (int mt = 0; mt < 2; mt++)
        #pragma unroll
        for (int q = 0; q < 4; q++)
          #pragma unroll
          for (int i = 0; i < 4; i++) acc[mt][q][i] = 0.f;

      #pragma unroll
      for (int kt = 0; kt < 4; kt++)
        #pragma unroll
        for (int q = 0; q < 4; q++) {
          int nt = 4 * h + q;
          u32 bh[2], bl[2];
          *(uint2*)bh = *(const uint2*)&bcur[((kt * 8 + nt) * 32 + lane) * 2];
          *(uint2*)bl = *(const uint2*)&bcur[2048 + ((kt * 8 + nt) * 32 + lane) * 2];
          #pragma unroll
          for (int mt = 0; mt < 2; mt++) {
            mma16816(acc[mt][q], A2h[mt][kt], bh);
            mma16816(acc[mt][q], A2h[mt][kt], bl);
            mma16816(acc[mt][q], A2l[mt][kt], bh);
          }
        }
      store_D_half(sD, w, g, c, h, acc);
    }

    __syncthreads();   // all warps done reading bcur; prior stage visible
    if (G <= 6)
      stage(t, bcur, &g_B2h[G + 2][0][0][0][0], &g_B2l[G + 2][0][0][0][0]);

    __syncwarp();

    switch (G) {
      case 0: epi<0>(drow, x0, xg, y0, y1x, y1y, y1z, z4, o0, o1); break;
      case 1: epi<1>(drow, x0, xg, y0, y1x, y1y, y1z, z4, o0, o1); break;
      case 2: epi<2>(drow, x0, xg, y0, y1x, y1y, y1z, z4, o0, o1); break;
      case 3: epi<3>(drow, x0, xg, y0, y1x, y1y, y1z, z4, o0, o1); break;
      case 4: epi<4>(drow, x0, xg, y0, y1x, y1y, y1z, z4, o0, o1); break;
      case 5: epi<5>(drow, x0, xg, y0, y1x, y1y, y1z, z4, o0, o1); break;
      case 6: epi<6>(drow, x0, xg, y0, y1x, y1y, y1z, z4, o0, o1); break;
      case 7: epi<7>(drow, x0, xg, y0, y1x, y1y, y1z, z4, o0, o1); break;
      case 8: epi<8>(drow, x0, xg, y0, y1x, y1y, y1z, z4, o0, o1); break;
    }
    __syncwarp();   // warp's D reads done before next chunk's store_D
  }

  // ---- scatter: 40 outputs for this lane's edge ----
  {
    const int base = my_src * 40;
    #pragma unroll
    for (int i = 0; i < 16; i++) atomicAdd(out + base + i, S0F * o0[i]);
    #pragma unroll
    for (int i = 0; i < 24; i++) atomicAdd(out + base + 16 + i, S0F * o1[i]);
  }
}

extern "C" void kernel_launch(void* const* d_in, const int* in_sizes, int n_in,
                              void* d_out, int out_size) {
  const float* node_input = (const float*)d_in[0];
  const int*   edge_src   = (const int*)d_in[1];
  const int*   edge_dst   = (const int*)d_in[2];
  const float* edge_attr  = (const float*)d_in[3];
  const float* dist       = (const float*)d_in[4];
  const float* W1         = (const float*)d_in[5];
  const float* W2         = (const float*)d_in[6];
  float* out = (float*)d_out;

  cudaFuncSetAttribute(fused_conv, cudaFuncAttributeMaxDynamicSharedMemorySize,
                       SMEM_BYTES);

  cudaMemsetAsync(out, 0, (size_t)out_size * sizeof(float));
  prep_frags<<<80, 128>>>(W1, W2);
  fused_conv<<<NBLK, 128, SMEM_BYTES>>>(node_input, edge_src, edge_dst,
                                        edge_attr, dist, out);
}

// round 10
// speedup vs baseline: 2.9986x; 1.3087x over previous
#include <cuda_runtime.h>
#include <cuda_fp16.h>
#include <cstdint>

#define N_EDGES   400000
#define TE        128
#define NBLK      (N_EDGES / TE)   // 3125, exact
#define WN        576
#define C3F       0.5773502691896257f
#define S0F       0.006378879538497861f   // sqrt(1/24)/32
#define SILU_NORM 1.6791767923989418f

typedef uint32_t u32;

// ---- weight fragment tables (fp16, mma.sync fragment order) ----------------
// layout: [chunk][kt][nt][lane][reg]; b: k = kt*16 + (lane%4)*2 (+8 for reg1),
// n = nt*8 + lane/4; value = half2(B[k][n], B[k+1][n]).
__device__ u32 g_B2[9][4][8][32][2];
__device__ u32 g_B1[4][8][32][2];

__device__ __forceinline__ int w2col(int mp) {
  int j = mp & 15, gr = mp >> 4, g = gr >> 2, r = gr & 3;
  if (g < 4) return j * 16 + r + 4 * g;
  if (g < 6) return 448 + (j & 7) * 16 + r + 4 * ((g - 4) * 2 + (j >> 3));
  if (g < 8) return 256 + j * 8 + 2 * r + (g - 6);
  return 384 + (j & 7) * 8 + 2 * r + (j >> 3);
}

// fp16 2-way split: v = hi + lo with hi = rn(v), lo = rn(v - hi)
__device__ __forceinline__ void split_pack_h(float v0, float v1, u32 &hi, u32 &lo) {
  __half h0 = __float2half_rn(v0), h1 = __float2half_rn(v1);
  __half l0 = __float2half_rn(v0 - __half2float(h0));
  __half l1 = __float2half_rn(v1 - __half2float(h1));
  __half2 H; H.x = h0; H.y = h1;
  __half2 L; L.x = l0; L.y = l1;
  hi = *(u32*)&H;  lo = *(u32*)&L;
}
__device__ __forceinline__ u32 pack_h(float v0, float v1) {
  __half2 H; H.x = __float2half_rn(v0); H.y = __float2half_rn(v1);
  return *(u32*)&H;
}

__global__ void prep_frags(const float* __restrict__ W1,
                           const float* __restrict__ W2) {
  int idx = blockIdx.x * blockDim.x + threadIdx.x;
  if (idx >= 10240) return;
  int lane = idx & 31;
  int nt = (idx >> 5) & 7;
  int kt = (idx >> 8) & 3;
  int C  = idx >> 10;                 // 0..8 = W2 chunks, 9 = W1
  int g = lane >> 2, c = lane & 3;
  int n = nt * 8 + g;
  #pragma unroll
  for (int r = 0; r < 2; r++) {
    int k = kt * 16 + c * 2 + r * 8;
    float v0, v1;
    if (C < 9) {
      int m = w2col(C * 64 + n);
      v0 = W2[k * WN + m];  v1 = W2[(k + 1) * WN + m];
    } else {
      v0 = W1[k * 64 + n];  v1 = W1[(k + 1) * 64 + n];
    }
    u32 hv = pack_h(v0, v1);
    if (C < 9) g_B2[C][kt][nt][lane][r] = hv;
    else       g_B1[kt][nt][lane][r]    = hv;
  }
}

__device__ __forceinline__ void mma16816h(float (&d)[4], const u32 (&a)[4],
                                          const u32 (&b)[2]) {
  asm volatile(
      "mma.sync.aligned.m16n8k16.row.col.f32.f16.f16.f32 "
      "{%0,%1,%2,%3}, {%4,%5,%6,%7}, {%8,%9}, {%0,%1,%2,%3};"
      : "+f"(d[0]), "+f"(d[1]), "+f"(d[2]), "+f"(d[3])
      : "r"(a[0]), "r"(a[1]), "r"(a[2]), "r"(a[3]), "r"(b[0]), "r"(b[1]));
}

// ---- smem layout (float offsets) -------------------------------------------
#define OFF_D   0          // 128*68 f32 (D tiles; also warp-private h stage)
#define OFF_B0  8704       // 2048 u32 (one fp16 chunk, 8KB)
#define OFF_B1  10752      // 2048 u32
#define SMEM_FLOATS 12800
#define SMEM_BYTES  (SMEM_FLOATS * 4)   // 51200 B

__device__ __forceinline__ void stage(int t, u32* dst, const u32* src) {
  #pragma unroll
  for (int i = 0; i < 4; i++)
    ((uint4*)dst)[t + i * 128] = ((const uint4*)src)[t + i * 128];
}

// store one nt-half (4 n-tiles) of the warp's D tile
__device__ __forceinline__ void store_D_half(float* sD, int w, int g, int c, int h,
                                             const float (&acc)[2][4][4]) {
  #pragma unroll
  for (int mt = 0; mt < 2; mt++) {
    int row0 = 32 * w + 16 * mt + g;
    #pragma unroll
    for (int q = 0; q < 4; q++) {
      int nc = (4 * h + q) * 8 + 2 * c;
      *(float2*)&sD[row0 * 68 + nc] = make_float2(acc[mt][q][0], acc[mt][q][1]);
      *(float2*)&sD[(row0 + 8) * 68 + nc] = make_float2(acc[mt][q][2], acc[mt][q][3]);
    }
  }
}

// ---- epilogue: tensor product for one 64-col chunk, one edge per lane ------
template <int G>
__device__ __forceinline__ void epi(const float* __restrict__ drow,
                                    const float (&x0)[16],
                                    const float* __restrict__ xg,
                                    float y0, float y1x, float y1y, float y1z,
                                    const float (&z4)[8],
                                    float (&o0)[16], float (&o1)[24]) {
  #pragma unroll
  for (int rr = 0; rr < 4; rr++) {
    float wv[16];
    #pragma unroll
    for (int i = 0; i < 4; i++)
      ((float4*)wv)[i] = *(const float4*)(drow + rr * 16 + 4 * i);

    if (G < 4) {
      float s = 0.f;
      #pragma unroll
      for (int j = 0; j < 16; j++) s += x0[j] * wv[j];
      o0[rr + 4 * G] += y0 * s;
    } else if (G < 6) {
      float sA = 0.f, sB = 0.f;
      #pragma unroll
      for (int u = 0; u < 8; u++) { sA += z4[u] * wv[u]; sB += z4[u] * wv[8 + u]; }
      o0[rr + 4 * (2 * (G - 4) + 0)] += C3F * sA;
      o0[rr + 4 * (2 * (G - 4) + 1)] += C3F * sB;
    } else if (G < 8) {
      float q = 0.f;
      #pragma unroll
      for (int j = 0; j < 16; j++) q += x0[j] * wv[j];
      const int ww = 2 * rr + (G - 6);
      o1[ww * 3 + 0] += q * y1x;  o1[ww * 3 + 1] += q * y1y;  o1[ww * 3 + 2] += q * y1z;
    } else {
      // x1 reloaded from global (L1-resident; only for this final chunk)
      #pragma unroll
      for (int hf = 0; hf < 2; hf++) {
        float s0 = 0.f, s1 = 0.f, s2 = 0.f;
        #pragma unroll
        for (int u = 0; u < 8; u++) {
          float wu = wv[hf * 8 + u];
          s0 += xg[16 + 3 * u + 0] * wu;
          s1 += xg[16 + 3 * u + 1] * wu;
          s2 += xg[16 + 3 * u + 2] * wu;
        }
        const int ww = 2 * rr + hf;
        o1[ww * 3 + 0] += y0 * s0;  o1[ww * 3 + 1] += y0 * s1;  o1[ww * 3 + 2] += y0 * s2;
      }
    }
  }
}

// ---- main kernel ------------------------------------------------------------
__global__ __launch_bounds__(128, 3) void fused_conv(
    const float* __restrict__ node_input,
    const int*   __restrict__ edge_src,
    const int*   __restrict__ edge_dst,
    const float* __restrict__ edge_attr,
    const float* __restrict__ dist,
    float* __restrict__ out)
{
  extern __shared__ float sm[];
  float* sD  = sm + OFF_D;
  u32*   sB0 = (u32*)(sm + OFF_B0);
  u32*   sB1 = (u32*)(sm + OFF_B1);

  const int t = threadIdx.x;
  const int lane = t & 31, w = t >> 5;
  const int g = lane >> 2, c = lane & 3;
  const long e0 = (long)blockIdx.x * TE;

  const int my_src = edge_src[e0 + t];
  const int my_dst = edge_dst[e0 + t];
  const float4 ya = ((const float4*)edge_attr)[e0 + t];
  const float y0 = ya.x, y1x = ya.y, y1y = ya.z, y1z = ya.w;
  const float* xg = node_input + (long)my_dst * 40;

  // per-lane node features: x0 in regs, z4 computed once
  float x0[16];
  #pragma unroll
  for (int i = 0; i < 4; i++) ((float4*)x0)[i] = *(const float4*)(xg + 4 * i);
  float z4[8];
  #pragma unroll
  for (int u = 0; u < 8; u++)
    z4[u] = xg[16 + 3 * u + 0] * y1x + xg[16 + 3 * u + 1] * y1y
          + xg[16 + 3 * u + 2] * y1z;

  // stage W1 frags -> B0, chunk0 -> B1
  stage(t, sB0, &g_B1[0][0][0][0]);
  stage(t, sB1, &g_B2[0][0][0][0][0]);
  __syncthreads();

  // ---- GEMM1: D = dist @ W1 (fp16 a-split, 2 passes) ----
  {
    float acc[2][8][4];
    #pragma unroll
    for (int mt = 0; mt < 2; mt++)
      #pragma unroll
      for (int nt = 0; nt < 8; nt++)
        #pragma unroll
        for (int i = 0; i < 4; i++) acc[mt][nt][i] = 0.f;

    #pragma unroll
    for (int kt = 0; kt < 4; kt++) {
      u32 ah[2][4], al[2][4];
      #pragma unroll
      for (int mt = 0; mt < 2; mt++) {
        int row0 = 32 * w + 16 * mt + g;
        const float* dp = dist + (e0 + row0) * 64 + kt * 16 + 2 * c;
        float2 f0 = *(const float2*)(dp);
        float2 f1 = *(const float2*)(dp + 8 * 64);
        float2 f2 = *(const float2*)(dp + 8);
        float2 f3 = *(const float2*)(dp + 8 * 64 + 8);
        split_pack_h(f0.x, f0.y, ah[mt][0], al[mt][0]);
        split_pack_h(f1.x, f1.y, ah[mt][1], al[mt][1]);
        split_pack_h(f2.x, f2.y, ah[mt][2], al[mt][2]);
        split_pack_h(f3.x, f3.y, ah[mt][3], al[mt][3]);
      }
      #pragma unroll
      for (int nt = 0; nt < 8; nt++) {
        u32 b[2];
        *(uint2*)b = *(const uint2*)&sB0[((kt * 8 + nt) * 32 + lane) * 2];
        #pragma unroll
        for (int mt = 0; mt < 2; mt++) {
          mma16816h(acc[mt][nt], ah[mt], b);
          mma16816h(acc[mt][nt], al[mt], b);
        }
      }
    }
    __syncthreads();   // all warps done reading B0 (W1)
    stage(t, sB0, &g_B2[1][0][0][0][0]);  // chunk1 -> B0

    #pragma unroll
    for (int mt = 0; mt < 2; mt++) {
      int row0 = 32 * w + 16 * mt + g;
      #pragma unroll
      for (int nt = 0; nt < 8; nt++) {
        *(float2*)&sD[row0 * 68 + nt * 8 + 2 * c] =
            make_float2(acc[mt][nt][0], acc[mt][nt][1]);
        *(float2*)&sD[(row0 + 8) * 68 + nt * 8 + 2 * c] =
            make_float2(acc[mt][nt][2], acc[mt][nt][3]);
      }
    }
    __syncwarp();
  }

  // silu on this lane's edge row (warp-private D slice)
  {
    float hv[64];
    #pragma unroll
    for (int i = 0; i < 16; i++)
      ((float4*)hv)[i] = *(const float4*)&sD[t * 68 + 4 * i];
    #pragma unroll
    for (int j = 0; j < 64; j++) {
      float v = hv[j] * 0.125f;
      hv[j] = SILU_NORM * v / (1.f + __expf(-v));
    }
    __syncwarp();   // warp's D reads done before overwrite

    // write h (fp16 split) into the warp's own D slice (132B row stride)
    char* hwarp = (char*)sD + 8704 * w;
    #pragma unroll
    for (int j = 0; j < 32; j++) {
      u32 hi, lo;  split_pack_h(hv[2 * j], hv[2 * j + 1], hi, lo);
      *(u32*)(hwarp + lane * 132 + 4 * j) = hi;
      *(u32*)(hwarp + 4224 + lane * 132 + 4 * j) = lo;
    }
    __syncwarp();
  }

  // load persistent A fragments of h (hi/lo) — within this warp's slice
  u32 A2h[2][4][4], A2l[2][4][4];
  {
    char* hwarp = (char*)sD + 8704 * w;
    #pragma unroll
    for (int mt = 0; mt < 2; mt++) {
      int rl = 16 * mt + g;
      #pragma unroll
      for (int kt = 0; kt < 4; kt++) {
        int cb = (kt * 16 + 2 * c) * 2;
        A2h[mt][kt][0] = *(const u32*)(hwarp + rl * 132 + cb);
        A2h[mt][kt][1] = *(const u32*)(hwarp + (rl + 8) * 132 + cb);
        A2h[mt][kt][2] = *(const u32*)(hwarp + rl * 132 + cb + 16);
        A2h[mt][kt][3] = *(const u32*)(hwarp + (rl + 8) * 132 + cb + 16);
        A2l[mt][kt][0] = *(const u32*)(hwarp + 4224 + rl * 132 + cb);
        A2l[mt][kt][1] = *(const u32*)(hwarp + 4224 + (rl + 8) * 132 + cb);
        A2l[mt][kt][2] = *(const u32*)(hwarp + 4224 + rl * 132 + cb + 16);
        A2l[mt][kt][3] = *(const u32*)(hwarp + 4224 + (rl + 8) * 132 + cb + 16);
      }
    }
    __syncwarp();   // A frag loads done -> warp slice reusable as D
  }

  float o0[16], o1[24];
  #pragma unroll
  for (int i = 0; i < 16; i++) o0[i] = 0.f;
  #pragma unroll
  for (int i = 0; i < 24; i++) o1[i] = 0.f;

  const float* drow = sD + t * 68;

  // ---- GEMM2 + tensor product, 9 chunks (nt split in two halves) ----
  #pragma unroll 1
  for (int G = 0; G < 9; G++) {
    u32* bcur = (G & 1) ? sB0 : sB1;   // chunk G lives here

    #pragma unroll
    for (int h = 0; h < 2; h++) {
      float acc[2][4][4];
      #pragma unroll
      for (int mt = 0; mt < 2; mt++)
        #pragma unroll
        for (int q = 0; q < 4; q++)
          #pragma unroll
          for (int i = 0; i < 4; i++) acc[mt][q][i] = 0.f;

      #pragma unroll
      for (int kt = 0; kt < 4; kt++)
        #pragma unroll
        for (int q = 0; q < 4; q++) {
          int nt = 4 * h + q;
          u32 b[2];
          *(uint2*)b = *(const uint2*)&bcur[((kt * 8 + nt) * 32 + lane) * 2];
          #pragma unroll
          for (int mt = 0; mt < 2; mt++) {
            mma16816h(acc[mt][q], A2h[mt][kt], b);
            mma16816h(acc[mt][q], A2l[mt][kt], b);
          }
        }
      store_D_half(sD, w, g, c, h, acc);
    }

    __syncthreads();   // all warps done reading bcur; prior stage visible
    if (G <= 6)
      stage(t, bcur, &g_B2[G + 2][0][0][0][0]);

    __syncwarp();

    switch (G) {
      case 0: epi<0>(drow, x0, xg, y0, y1x, y1y, y1z, z4, o0, o1); break;
      case 1: epi<1>(drow, x0, xg, y0, y1x, y1y, y1z, z4, o0, o1); break;
      case 2: epi<2>(drow, x0, xg, y0, y1x, y1y, y1z, z4, o0, o1); break;
      case 3: epi<3>(drow, x0, xg, y0, y1x, y1y, y1z, z4, o0, o1); break;
      case 4: epi<4>(drow, x0, xg, y0, y1x, y1y, y1z, z4, o0, o1); break;
      case 5: epi<5>(drow, x0, xg, y0, y1x, y1y, y1z, z4, o0, o1); break;
      case 6: epi<6>(drow, x0, xg, y0, y1x, y1y, y1z, z4, o0, o1); break;
      case 7: epi<7>(drow, x0, xg, y0, y1x, y1y, y1z, z4, o0, o1); break;
      case 8: epi<8>(drow, x0, xg, y0, y1x, y1y, y1z, z4, o0, o1); break;
    }
    __syncwarp();   // warp's D reads done before next chunk's store_D
  }

  // ---- scatter: 40 outputs for this lane's edge ----
  {
    const int base = my_src * 40;
    #pragma unroll
    for (int i = 0; i < 16; i++) atomicAdd(out + base + i, S0F * o0[i]);
    #pragma unroll
    for (int i = 0; i < 24; i++) atomicAdd(out + base + 16 + i, S0F * o1[i]);
  }
}

extern "C" void kernel_launch(void* const* d_in, const int* in_sizes, int n_in,
                              void* d_out, int out_size) {
  const float* node_input = (const float*)d_in[0];
  const int*   edge_src   = (const int*)d_in[1];
  const int*   edge_dst   = (const int*)d_in[2];
  const float* edge_attr  = (const float*)d_in[3];
  const float* dist       = (const float*)d_in[4];
  const float* W1         = (const float*)d_in[5];
  const float* W2         = (const float*)d_in[6];
  float* out = (float*)d_out;

  cudaFuncSetAttribute(fused_conv, cudaFuncAttributeMaxDynamicSharedMemorySize,
                       SMEM_BYTES);

  cudaMemsetAsync(out, 0, (size_t)out_size * sizeof(float));
  prep_frags<<<80, 128>>>(W1, W2);
  fused_conv<<<NBLK, 128, SMEM_BYTES>>>(node_input, edge_src, edge_dst,
                                        edge_attr, dist, out);
}

// round 11
// speedup vs baseline: 3.8045x; 1.2688x over previous
#include <cuda_runtime.h>
#include <cuda_fp16.h>
#include <cstdint>

#define N_EDGES   400000
#define TE        128
#define NBLK      (N_EDGES / TE)   // 3125, exact
#define WN        576
#define C3F       0.5773502691896257f
#define S0F       0.006378879538497861f   // sqrt(1/24)/32
#define SILU_NORM 1.6791767923989418f

typedef uint32_t u32;

// ---- weight fragment tables (fp16, mma.sync fragment order) ----------------
__device__ u32 g_B2[9][4][8][32][2];
__device__ u32 g_B1[4][8][32][2];

__device__ __forceinline__ int w2col(int mp) {
  int j = mp & 15, gr = mp >> 4, g = gr >> 2, r = gr & 3;
  if (g < 4) return j * 16 + r + 4 * g;
  if (g < 6) return 448 + (j & 7) * 16 + r + 4 * ((g - 4) * 2 + (j >> 3));
  if (g < 8) return 256 + j * 8 + 2 * r + (g - 6);
  return 384 + (j & 7) * 8 + 2 * r + (j >> 3);
}

__device__ __forceinline__ void split_pack_h(float v0, float v1, u32 &hi, u32 &lo) {
  __half h0 = __float2half_rn(v0), h1 = __float2half_rn(v1);
  __half l0 = __float2half_rn(v0 - __half2float(h0));
  __half l1 = __float2half_rn(v1 - __half2float(h1));
  __half2 H; H.x = h0; H.y = h1;
  __half2 L; L.x = l0; L.y = l1;
  hi = *(u32*)&H;  lo = *(u32*)&L;
}
__device__ __forceinline__ u32 pack_h(float v0, float v1) {
  __half2 H; H.x = __float2half_rn(v0); H.y = __float2half_rn(v1);
  return *(u32*)&H;
}

__global__ void prep_frags(const float* __restrict__ W1,
                           const float* __restrict__ W2) {
  int idx = blockIdx.x * blockDim.x + threadIdx.x;
  if (idx >= 10240) return;
  int lane = idx & 31;
  int nt = (idx >> 5) & 7;
  int kt = (idx >> 8) & 3;
  int C  = idx >> 10;                 // 0..8 = W2 chunks, 9 = W1
  int g = lane >> 2, c = lane & 3;
  int n = nt * 8 + g;
  #pragma unroll
  for (int r = 0; r < 2; r++) {
    int k = kt * 16 + c * 2 + r * 8;
    float v0, v1;
    if (C < 9) {
      int m = w2col(C * 64 + n);
      v0 = W2[k * WN + m];  v1 = W2[(k + 1) * WN + m];
    } else {
      v0 = W1[k * 64 + n];  v1 = W1[(k + 1) * 64 + n];
    }
    u32 hv = pack_h(v0, v1);
    if (C < 9) g_B2[C][kt][nt][lane][r] = hv;
    else       g_B1[kt][nt][lane][r]    = hv;
  }
}

__device__ __forceinline__ void mma16816h(float (&d)[4], const u32 (&a)[4],
                                          const u32 (&b)[2]) {
  asm volatile(
      "mma.sync.aligned.m16n8k16.row.col.f32.f16.f16.f32 "
      "{%0,%1,%2,%3}, {%4,%5,%6,%7}, {%8,%9}, {%0,%1,%2,%3};"
      : "+f"(d[0]), "+f"(d[1]), "+f"(d[2]), "+f"(d[3])
      : "r"(a[0]), "r"(a[1]), "r"(a[2]), "r"(a[3]), "r"(b[0]), "r"(b[1]));
}

#define SMEM_BYTES 16384   // two 8KB fp16 B buffers

__device__ __forceinline__ void stage(int t, u32* dst, const u32* src) {
  #pragma unroll
  for (int i = 0; i < 4; i++)
    ((uint4*)dst)[t + i * 128] = ((const uint4*)src)[t + i * 128];
}

// ---- fragment-side epilogue for one half (nt = 4h..4h+3) -------------------
template <int G>
__device__ __forceinline__ void epi_half(
    int h, int c, const float (&acc)[2][4][4],
    const float (&x0v)[4][4], const float (&y0v)[4],
    const float (&z4v)[4][2], const float (&y1v)[4][3], const float (&x1v)[4][6],
    float (&oA)[4][4], float (&oB)[4][2][3])
{
  if (G < 4 || G == 6 || G == 7) {            // x0-dot classes (w1, w2)
    float P[4][2] = {};
    #pragma unroll
    for (int q = 0; q < 4; q++) {
      const int rrl = q >> 1, js = (q & 1) * 2;
      #pragma unroll
      for (int mt = 0; mt < 2; mt++) {
        P[2*mt+0][rrl] += acc[mt][q][0]*x0v[2*mt+0][js] + acc[mt][q][1]*x0v[2*mt+0][js+1];
        P[2*mt+1][rrl] += acc[mt][q][2]*x0v[2*mt+1][js] + acc[mt][q][3]*x0v[2*mt+1][js+1];
      }
    }
    #pragma unroll
    for (int rrl = 0; rrl < 2; rrl++)
      #pragma unroll
      for (int slot = 0; slot < 4; slot++) {
        float v = P[slot][rrl];
        v += __shfl_xor_sync(0xffffffffu, v, 1);
        v += __shfl_xor_sync(0xffffffffu, v, 2);
        if (c == 2*h + rrl) {
          if (G < 4) {
            oA[slot][G] += y0v[slot] * v;
          } else {
            oB[slot][G-6][0] += v * y1v[slot][0];
            oB[slot][G-6][1] += v * y1v[slot][1];
            oB[slot][G-6][2] += v * y1v[slot][2];
          }
        }
      }
  } else if (G < 6) {                          // w4: z4-dot, sA/sB per rr
    float P[4][2][2] = {};
    #pragma unroll
    for (int q = 0; q < 4; q++) {
      const int rrl = q >> 1, sel = q & 1;
      #pragma unroll
      for (int mt = 0; mt < 2; mt++) {
        P[2*mt+0][rrl][sel] += acc[mt][q][0]*z4v[2*mt+0][0] + acc[mt][q][1]*z4v[2*mt+0][1];
        P[2*mt+1][rrl][sel] += acc[mt][q][2]*z4v[2*mt+1][0] + acc[mt][q][3]*z4v[2*mt+1][1];
      }
    }
    #pragma unroll
    for (int rrl = 0; rrl < 2; rrl++)
      #pragma unroll
      for (int slot = 0; slot < 4; slot++)
        #pragma unroll
        for (int sel = 0; sel < 2; sel++) {
          float v = P[slot][rrl][sel];
          v += __shfl_xor_sync(0xffffffffu, v, 1);
          v += __shfl_xor_sync(0xffffffffu, v, 2);
          if (c == 2*h + rrl) oA[slot][2*(G-4)+sel] += C3F * v;
        }
  } else {                                     // G == 8, w3: x1-weighted
    #pragma unroll
    for (int q = 0; q < 4; q++) {
      const int rrl = q >> 1, hf = q & 1;
      float S[4][3] = {};
      #pragma unroll
      for (int mt = 0; mt < 2; mt++)
        #pragma unroll
        for (int i = 0; i < 3; i++) {
          S[2*mt+0][i] += acc[mt][q][0]*x1v[2*mt+0][i] + acc[mt][q][1]*x1v[2*mt+0][3+i];
          S[2*mt+1][i] += acc[mt][q][2]*x1v[2*mt+1][i] + acc[mt][q][3]*x1v[2*mt+1][3+i];
        }
      #pragma unroll
      for (int slot = 0; slot < 4; slot++)
        #pragma unroll
        for (int i = 0; i < 3; i++) {
          float v = S[slot][i];
          v += __shfl_xor_sync(0xffffffffu, v, 1);
          v += __shfl_xor_sync(0xffffffffu, v, 2);
          if (c == 2*h + rrl) oB[slot][hf][i] += y0v[slot] * v;
        }
    }
  }
}

// ---- one GEMM2 chunk: MMA (both halves) + fragment epilogue ----------------
template <int G>
__device__ __forceinline__ void chunk_proc(
    int lane, int c, const u32* __restrict__ bcur,
    const u32 (&A2h)[2][4][4], const u32 (&A2l)[2][4][4],
    const float (&x0v)[4][4], const float (&y0v)[4],
    const int (&rowE)[4], const int (&dstE)[4],
    const float* __restrict__ node_input, const float* __restrict__ edge_attr,
    float (&oA)[4][4], float (&oB)[4][2][3])
{
  float z4v[4][2];  float y1v[4][3];  float x1v[4][6];
  if (G == 4 || G == 5) {
    #pragma unroll
    for (int slot = 0; slot < 4; slot++) {
      float4 ya = ((const float4*)edge_attr)[rowE[slot]];
      const float* xp = node_input + (long)dstE[slot] * 40 + 16 + 6 * c;
      z4v[slot][0] = xp[0]*ya.y + xp[1]*ya.z + xp[2]*ya.w;
      z4v[slot][1] = xp[3]*ya.y + xp[4]*ya.z + xp[5]*ya.w;
    }
  }
  if (G == 6 || G == 7) {
    #pragma unroll
    for (int slot = 0; slot < 4; slot++) {
      float4 ya = ((const float4*)edge_attr)[rowE[slot]];
      y1v[slot][0] = ya.y;  y1v[slot][1] = ya.z;  y1v[slot][2] = ya.w;
    }
  }
  if (G == 8) {
    #pragma unroll
    for (int slot = 0; slot < 4; slot++) {
      const float* xp = node_input + (long)dstE[slot] * 40 + 16 + 6 * c;
      #pragma unroll
      for (int i = 0; i < 6; i++) x1v[slot][i] = xp[i];
    }
  }

  #pragma unroll
  for (int h = 0; h < 2; h++) {
    float acc[2][4][4];
    #pragma unroll
    for (int mt = 0; mt < 2; mt++)
      #pragma unroll
      for (int q = 0; q < 4; q++)
        #pragma unroll
        for (int i = 0; i < 4; i++) acc[mt][q][i] = 0.f;

    #pragma unroll
    for (int kt = 0; kt < 4; kt++)
      #pragma unroll
      for (int q = 0; q < 4; q++) {
        const int nt = 4 * h + q;
        u32 b[2];
        *(uint2*)b = *(const uint2*)&bcur[((kt * 8 + nt) * 32 + lane) * 2];
        #pragma unroll
        for (int mt = 0; mt < 2; mt++) {
          mma16816h(acc[mt][q], A2h[mt][kt], b);
          mma16816h(acc[mt][q], A2l[mt][kt], b);
        }
      }
    epi_half<G>(h, c, acc, x0v, y0v, z4v, y1v, x1v, oA, oB);
  }
}

// ---- main kernel ------------------------------------------------------------
__global__ __launch_bounds__(128, 3) void fused_conv(
    const float* __restrict__ node_input,
    const int*   __restrict__ edge_src,
    const int*   __restrict__ edge_dst,
    const float* __restrict__ edge_attr,
    const float* __restrict__ dist,
    float* __restrict__ out)
{
  extern __shared__ u32 smu[];
  u32* sB0 = smu;
  u32* sB1 = smu + 2048;

  const int t = threadIdx.x;
  const int lane = t & 31, w = t >> 5;
  const int g = lane >> 2, c = lane & 3;
  const int e0 = blockIdx.x * TE;

  // per-lane row metadata (4 rows: slot = 2*mt + s -> row 32w+16mt+8s+g)
  int rowE[4], dstE[4];
  float y0v[4];
  #pragma unroll
  for (int slot = 0; slot < 4; slot++) {
    rowE[slot] = e0 + 32 * w + 16 * (slot >> 1) + 8 * (slot & 1) + g;
    dstE[slot] = edge_dst[rowE[slot]];
    y0v[slot]  = edge_attr[rowE[slot] * 4];
  }

  // stage W1 frags -> B0, chunk0 -> B1
  stage(t, sB0, &g_B1[0][0][0][0]);
  stage(t, sB1, &g_B2[0][0][0][0][0]);
  __syncthreads();

  // ---- GEMM1: D = dist @ W1 (fp16 a-split, 2 passes), full accumulators ----
  float acc1[2][8][4];
  #pragma unroll
  for (int mt = 0; mt < 2; mt++)
    #pragma unroll
    for (int nt = 0; nt < 8; nt++)
      #pragma unroll
      for (int i = 0; i < 4; i++) acc1[mt][nt][i] = 0.f;

  #pragma unroll
  for (int kt = 0; kt < 4; kt++) {
    u32 ah[2][4], al[2][4];
    #pragma unroll
    for (int mt = 0; mt < 2; mt++) {
      const int row0 = 32 * w + 16 * mt + g;
      const float* dp = dist + (long)(e0 + row0) * 64 + kt * 16 + 2 * c;
      float2 f0 = *(const float2*)(dp);
      float2 f1 = *(const float2*)(dp + 8 * 64);
      float2 f2 = *(const float2*)(dp + 8);
      float2 f3 = *(const float2*)(dp + 8 * 64 + 8);
      split_pack_h(f0.x, f0.y, ah[mt][0], al[mt][0]);
      split_pack_h(f1.x, f1.y, ah[mt][1], al[mt][1]);
      split_pack_h(f2.x, f2.y, ah[mt][2], al[mt][2]);
      split_pack_h(f3.x, f3.y, ah[mt][3], al[mt][3]);
    }
    #pragma unroll
    for (int nt = 0; nt < 8; nt++) {
      u32 b[2];
      *(uint2*)b = *(const uint2*)&sB0[((kt * 8 + nt) * 32 + lane) * 2];
      #pragma unroll
      for (int mt = 0; mt < 2; mt++) {
        mma16816h(acc1[mt][nt], ah[mt], b);
        mma16816h(acc1[mt][nt], al[mt], b);
      }
    }
  }
  __syncthreads();                       // all warps done reading B0 (W1)
  stage(t, sB0, &g_B2[1][0][0][0][0]);   // chunk1 -> B0

  // silu on accumulators, pack directly into GEMM2 A fragments (no smem!)
  u32 A2h[2][4][4], A2l[2][4][4];
  #pragma unroll
  for (int mt = 0; mt < 2; mt++)
    #pragma unroll
    for (int kt = 0; kt < 4; kt++)
      #pragma unroll
      for (int idx = 0; idx < 4; idx++) {
        const int nt = 2 * kt + (idx >> 1);
        const int o  = (idx & 1) * 2;
        float v0 = acc1[mt][nt][o + 0] * 0.125f;
        float v1 = acc1[mt][nt][o + 1] * 0.125f;
        float h0 = SILU_NORM * v0 / (1.f + __expf(-v0));
        float h1 = SILU_NORM * v1 / (1.f + __expf(-v1));
        split_pack_h(h0, h1, A2h[mt][kt][idx], A2l[mt][kt][idx]);
      }

  // x0 fragment values: x0 at j in {2c,2c+1,8+2c,8+2c+1} for each of 4 rows
  float x0v[4][4];
  #pragma unroll
  for (int slot = 0; slot < 4; slot++) {
    const float* xp = node_input + (long)dstE[slot] * 40;
    float2 a = *(const float2*)(xp + 2 * c);
    float2 b = *(const float2*)(xp + 8 + 2 * c);
    x0v[slot][0] = a.x;  x0v[slot][1] = a.y;
    x0v[slot][2] = b.x;  x0v[slot][3] = b.y;
  }

  float oA[4][4];  float oB[4][2][3];
  #pragma unroll
  for (int s = 0; s < 4; s++) {
    #pragma unroll
    for (int i = 0; i < 4; i++) oA[s][i] = 0.f;
    #pragma unroll
    for (int p = 0; p < 2; p++)
      #pragma unroll
      for (int i = 0; i < 3; i++) oB[s][p][i] = 0.f;
  }

  float z4d[4][2];  float y1d[4][3];  float x1d[4][6];  // dummies for template
  (void)z4d; (void)y1d; (void)x1d;

  #define CH(G, BUF) chunk_proc<G>(lane, c, BUF, A2h, A2l, x0v, y0v, rowE, dstE, \
                                   node_input, edge_attr, oA, oB)
  CH(0, sB1);  __syncthreads();  stage(t, sB1, &g_B2[2][0][0][0][0]);
  CH(1, sB0);  __syncthreads();  stage(t, sB0, &g_B2[3][0][0][0][0]);
  CH(2, sB1);  __syncthreads();  stage(t, sB1, &g_B2[4][0][0][0][0]);
  CH(3, sB0);  __syncthreads();  stage(t, sB0, &g_B2[5][0][0][0][0]);
  CH(4, sB1);  __syncthreads();  stage(t, sB1, &g_B2[6][0][0][0][0]);
  CH(5, sB0);  __syncthreads();  stage(t, sB0, &g_B2[7][0][0][0][0]);

  // scatter o0 outputs now (complete after w1 + w4 chunks); frees registers
  #pragma unroll
  for (int slot = 0; slot < 4; slot++) {
    const int base = edge_src[rowE[slot]] * 40;
    #pragma unroll
    for (int m = 0; m < 4; m++)
      atomicAdd(out + base + c + 4 * m, S0F * oA[slot][m]);
  }

  CH(6, sB1);  __syncthreads();  stage(t, sB1, &g_B2[8][0][0][0][0]);
  CH(7, sB0);  __syncthreads();
  CH(8, sB1);
  #undef CH

  // scatter o1 outputs
  #pragma unroll
  for (int slot = 0; slot < 4; slot++) {
    const int base = edge_src[rowE[slot]] * 40;
    #pragma unroll
    for (int sp = 0; sp < 2; sp++)
      #pragma unroll
      for (int i = 0; i < 3; i++)
        atomicAdd(out + base + 16 + (2 * c + sp) * 3 + i,
                  S0F * oB[slot][sp][i]);
  }
}

extern "C" void kernel_launch(void* const* d_in, const int* in_sizes, int n_in,
                              void* d_out, int out_size) {
  const float* node_input = (const float*)d_in[0];
  const int*   edge_src   = (const int*)d_in[1];
  const int*   edge_dst   = (const int*)d_in[2];
  const float* edge_attr  = (const float*)d_in[3];
  const float* dist       = (const float*)d_in[4];
  const float* W1         = (const float*)d_in[5];
  const float* W2         = (const float*)d_in[6];
  float* out = (float*)d_out;

  cudaMemsetAsync(out, 0, (size_t)out_size * sizeof(float));
  prep_frags<<<80, 128>>>(W1, W2);
  fused_conv<<<NBLK, 128, SMEM_BYTES>>>(node_input, edge_src, edge_dst,
                                        edge_attr, dist, out);
}